// round 11
// baseline (speedup 1.0000x reference)
#include <cuda_runtime.h>
#include <cuda_fp16.h>
#include <math_constants.h>
#include <cstdint>

#define NROWS 16384
#define DIM   256
#define KCB   8192
#define MT    128                /* m rows per CTA          */
#define MTILES (NROWS / MT)      /* 128 m-tiles             */
#define NHALFS 2                 /* N split across CTAs     */
#define CODES_HALF (KCB / NHALFS)
#define NT_CTA (CODES_HALF / 128)/* 32 n-tiles per CTA      */
#define NSTAGE (NT_CTA * 4)      /* 128 k64 stages per CTA  */
#define NPART (NROWS / 8)

/* GEMM smem layout (dynamic) */
#define SA_OFF  0                /* A fp16: 128 rows x 512B = 64KB     */
#define SB_OFF  65536            /* 2 x 16KB B stage double buffer     */
#define SCN_OFF 98304            /* 2 x 512B codenorm tiles            */
#define GEMM_SMEM 99328

/* ------------- device globals (no allocs allowed) ------------- */
__device__ unsigned char g_zt[MTILES * 65536];            /* 8MB pre-swizzled A fp16       */
__device__ unsigned char g_cbt[NHALFS * NSTAGE * 16384];  /* 4MB pre-swizzled B fp16 stages*/
__device__ float g_codenorm[KCB];
__device__ int   g_cand[NROWS * 8];
__device__ float g_losspart[NPART];
__device__ unsigned g_ctr;

/* ------------- helpers ------------- */
__device__ __forceinline__ unsigned smem_u32(const void* p) {
    unsigned a;
    asm("{ .reg .u64 t; cvta.to.shared.u64 t, %1; cvt.u32.u64 %0, t; }" : "=r"(a) : "l"(p));
    return a;
}
__device__ __forceinline__ void cp_async16(unsigned dst, const void* src) {
    asm volatile("cp.async.cg.shared.global [%0], [%1], 16;" :: "r"(dst), "l"(src) : "memory");
}
/* volatile is load-bearing: without it the compiler may hoist/CSE these smem
   reads across cp.async.wait_group/__syncthreads into the wrong buffer epoch */
__device__ __forceinline__ void ldsm_x4(unsigned* r, unsigned addr) {
    asm volatile("ldmatrix.sync.aligned.m8n8.x4.shared.b16 {%0,%1,%2,%3}, [%4];"
                 : "=r"(r[0]), "=r"(r[1]), "=r"(r[2]), "=r"(r[3]) : "r"(addr));
}
__device__ __forceinline__ void mma16816(float (&c)[4], const unsigned* a, unsigned b0, unsigned b1) {
    asm volatile("mma.sync.aligned.m16n8k16.row.col.f32.f16.f16.f32 "
                 "{%0,%1,%2,%3}, {%4,%5,%6,%7}, {%8,%9}, {%0,%1,%2,%3};"
                 : "+f"(c[0]), "+f"(c[1]), "+f"(c[2]), "+f"(c[3])
                 : "r"(a[0]), "r"(a[1]), "r"(a[2]), "r"(a[3]), "r"(b0), "r"(b1));
}
/* top-2 with both indices packed into one reg (codes < 8192 fit in 16 bits) */
__device__ __forceinline__ void top2p(float& v1, float& v2, unsigned& ti, float d, unsigned c) {
    if (d < v2) {
        if (d < v1) { v2 = v1; ti = (ti << 16) | c; v1 = d; }
        else        { v2 = d;  ti = (ti & 0xFFFFu) | (c << 16); }
    }
}
__device__ __forceinline__ void ins4(float (&cv)[4], int (&ci)[4], float v, int i) {
#pragma unroll
    for (int j = 0; j < 4; j++) {
        bool lt = (v < cv[j]) || (v == cv[j] && i < ci[j]);
        float tv = lt ? cv[j] : v; int ti = lt ? ci[j] : i;
        if (lt) { cv[j] = v; ci[j] = i; }
        v = tv; i = ti;
    }
}

/* ---------- preprocess: z -> swizzled fp16 tiles (128 rows x 512B, full k) ---------- */
__global__ void split_z_kernel(const float* __restrict__ z) {
    const int id = blockIdx.x * 256 + threadIdx.x;   /* 0..524287 */
    const int row = id >> 5;
    const int j = id & 31;                           /* 16B chunk (8 fp16) along k */
    const float* src = z + (size_t)row * DIM + j * 8;
    float4 f0 = __ldg((const float4*)src);
    float4 f1 = __ldg((const float4*)(src + 4));
    float v[8] = {f0.x, f0.y, f0.z, f0.w, f1.x, f1.y, f1.z, f1.w};
    unsigned short hv[8];
#pragma unroll
    for (int e = 0; e < 8; e++) hv[e] = __half_as_ushort(__float2half_rn(v[e]));
    size_t base = (size_t)(row >> 7) * 65536 + (size_t)(row & 127) * 512 + ((j ^ (row & 7)) << 4);
    *(uint4*)(g_zt + base) = *(uint4*)hv;
}

/* ---------- preprocess: codebook -> n-major swizzled fp16 k64 stages ---------- */
__global__ void split_cb_kernel(const float* __restrict__ cb) {
    const int id = blockIdx.x * 256 + threadIdx.x;   /* 0..262143 */
    const int n = id >> 5;                           /* code row 0..8191 */
    const int j = id & 31;                           /* 16B chunk over full k256 */
    const float* src = cb + (size_t)n * DIM + j * 8;
    float4 f0 = __ldg((const float4*)src);
    float4 f1 = __ldg((const float4*)(src + 4));
    float v[8] = {f0.x, f0.y, f0.z, f0.w, f1.x, f1.y, f1.z, f1.w};
    unsigned short hv[8];
#pragma unroll
    for (int e = 0; e < 8; e++) hv[e] = __half_as_ushort(__float2half_rn(v[e]));
    const int q = j >> 3, kb = j & 7;                /* k64 quarter, chunk within */
    const int hf = n >> 12, nt = (n >> 7) & 31, nr = n & 127;
    size_t base = ((size_t)(hf * NSTAGE + nt * 4 + q)) * 16384
                + (size_t)nr * 128 + ((kb ^ (nr & 7)) << 4);
    *(uint4*)(g_cbt + base) = *(uint4*)hv;
}

/* ---------- exact fp32 codebook norms ---------- */
__global__ void codenorm_kernel(const float* __restrict__ cb) {
    int warp = threadIdx.x >> 5, lane = threadIdx.x & 31;
    int row = blockIdx.x * 8 + warp;
    const float4* c4 = (const float4*)(cb + (size_t)row * DIM);
    float s = 0.f;
#pragma unroll
    for (int l = 0; l < 2; l++) {
        float4 v = c4[lane + 32 * l];
        s += v.x * v.x + v.y * v.y + v.z * v.z + v.w * v.w;
    }
#pragma unroll
    for (int o = 16; o > 0; o >>= 1) s += __shfl_down_sync(0xffffffffu, s, o);
    if (lane == 0) g_codenorm[row] = s;
}

/* ---------- stage producer: 16KB into buffer (s&1) (+ cn tile on quarter 0) ---------- */
__device__ __forceinline__ void issue_stage(unsigned smb, int s, int hf, int tid) {
    const unsigned char* src = g_cbt + ((size_t)(hf * NSTAGE + s)) * 16384 + tid * 16;
    unsigned dst = smb + SB_OFF + (s & 1) * 16384 + tid * 16;
#pragma unroll
    for (int i = 0; i < 4; i++) cp_async16(dst + i * 4096, src + (size_t)i * 4096);
    if ((s & 3) == 0 && tid < 32)
        cp_async16(smb + SCN_OFF + ((s >> 2) & 1) * 512 + tid * 16,
                   (const unsigned char*)g_codenorm + (size_t)hf * 16384 + (size_t)(s >> 2) * 512 + tid * 16);
    asm volatile("cp.async.commit_group;" ::: "memory");
}

/* ---------- compute one k64 quarter: 4 k16-steps, warp tile 64m x 32n ---------- */
template<int Q, int BUF>
__device__ __forceinline__ void compute_quarter(float (&acc)[4][4][4], unsigned smb,
                                                int wm, int wn, int lane) {
    const int lm = lane & 15;
    const int sel = lane >> 4;
    const int xa = lm & 7;
    unsigned abase[4];
#pragma unroll
    for (int mi = 0; mi < 4; mi++)
        abase[mi] = smb + SA_OFF + (wm * 64 + mi * 16 + lm) * 512 + Q * 128;
    const unsigned bb = smb + SB_OFF + BUF * 16384 + (wn * 32 + lm) * 128;
    const unsigned b1off = 16 * 128;
#pragma unroll
    for (int ks = 0; ks < 4; ks++) {
        const unsigned off = (unsigned)(((ks * 2 + sel) ^ xa) << 4);
        unsigned a[4][4], b[2][4];
#pragma unroll
        for (int mi = 0; mi < 4; mi++) ldsm_x4(a[mi], abase[mi] + off);
        ldsm_x4(b[0], bb + off);
        ldsm_x4(b[1], bb + b1off + off);
#pragma unroll
        for (int mi = 0; mi < 4; mi++) {
            mma16816(acc[mi][0], a[mi], b[0][0], b[0][2]);
            mma16816(acc[mi][1], a[mi], b[0][1], b[0][3]);
            mma16816(acc[mi][2], a[mi], b[1][0], b[1][2]);
            mma16816(acc[mi][3], a[mi], b[1][1], b[1][3]);
        }
    }
}

#define WAIT_SYNC() do { \
    asm volatile("cp.async.wait_group 0;" ::: "memory"); \
    __syncthreads(); \
} while (0)

/* ---------- K1: fp16 tensor GEMM (128m x 4096n per CTA) + fused top-2 argmin ---------- */
__global__ void __launch_bounds__(256, 2) vq_mma_kernel() {
    extern __shared__ __align__(128) unsigned char smem[];
    const unsigned smb = smem_u32(smem);
    const int tid = threadIdx.x;
    const int lane = tid & 31;
    const int w = tid >> 5;
    const int wm = w >> 2, wn = w & 3;       /* 2m x 4n warp grid */
    const int hf = blockIdx.x;               /* N half            */
    const int mtile = blockIdx.y;            /* 128-row m tile    */

    if (hf == 0 && mtile == 0 && tid == 0) g_ctr = 0;

    { /* prologue group: resident A (64KB) + stage 0 + cn tile 0 */
        const unsigned char* src = g_zt + (size_t)mtile * 65536 + tid * 16;
        unsigned dst = smb + SA_OFF + tid * 16;
#pragma unroll
        for (int i = 0; i < 16; i++) cp_async16(dst + i * 4096, src + (size_t)i * 4096);
        issue_stage(smb, 0, hf, tid);
    }

    float acc[4][4][4];
#pragma unroll
    for (int i = 0; i < 4; i++)
#pragma unroll
        for (int j = 0; j < 4; j++)
#pragma unroll
            for (int r = 0; r < 4; r++) acc[i][j][r] = 0.f;
    float tv1[8], tv2[8];
    unsigned tip[8];
#pragma unroll
    for (int sl = 0; sl < 8; sl++) { tv1[sl] = CUDART_INF_F; tv2[sl] = CUDART_INF_F; tip[sl] = 0; }

    const int colb = wn * 32 + 2 * (lane & 3);
    for (int nt = 0; nt < NT_CTA; nt++) {
        const int s0 = nt * 4;
        WAIT_SYNC(); issue_stage(smb, s0 + 1, hf, tid);
        compute_quarter<0, 0>(acc, smb, wm, wn, lane);
        WAIT_SYNC(); issue_stage(smb, s0 + 2, hf, tid);
        compute_quarter<1, 1>(acc, smb, wm, wn, lane);
        WAIT_SYNC(); issue_stage(smb, s0 + 3, hf, tid);
        compute_quarter<2, 0>(acc, smb, wm, wn, lane);
        WAIT_SYNC();
        if (nt + 1 < NT_CTA) issue_stage(smb, s0 + 4, hf, tid);
        compute_quarter<3, 1>(acc, smb, wm, wn, lane);
        { /* epilogue: dist + packed top-2, zero acc */
            const float* cnp = (const float*)(smem + SCN_OFF + (nt & 1) * 512);
            const unsigned cbase = (unsigned)(hf * CODES_HALF + nt * 128 + colb);
#pragma unroll
            for (int ni = 0; ni < 4; ni++) {
                float cn0 = cnp[colb + ni * 8];
                float cn1 = cnp[colb + ni * 8 + 1];
                unsigned c0 = cbase + ni * 8;
#pragma unroll
                for (int mi = 0; mi < 4; mi++) {
#pragma unroll
                    for (int h = 0; h < 2; h++) {
                        int sl = mi * 2 + h;
                        float d0 = fmaf(-2.f, acc[mi][ni][h * 2],     cn0);
                        float d1 = fmaf(-2.f, acc[mi][ni][h * 2 + 1], cn1);
                        top2p(tv1[sl], tv2[sl], tip[sl], d0, c0);
                        top2p(tv1[sl], tv2[sl], tip[sl], d1, c0 + 1);
                        acc[mi][ni][h * 2] = 0.f;
                        acc[mi][ni][h * 2 + 1] = 0.f;
                    }
                }
            }
        }
    }

    /* dump all 32 per-row candidates, then per-row top-4 merge */
    __syncthreads();
    float4* red = (float4*)(smem + SB_OFF);    /* 128 rows x 16 entries x 16B = 32KB */
#pragma unroll
    for (int sl = 0; sl < 8; sl++) {
        int mi = sl >> 1, h = sl & 1;
        int row = wm * 64 + mi * 16 + h * 8 + (lane >> 2);
        red[row * 16 + wn * 4 + (lane & 3)] =
            make_float4(tv1[sl], __int_as_float((int)(tip[sl] & 0xFFFFu)),
                        tv2[sl], __int_as_float((int)(tip[sl] >> 16)));
    }
    __syncthreads();
    if (tid < 128) {
        float cv[4] = {CUDART_INF_F, CUDART_INF_F, CUDART_INF_F, CUDART_INF_F};
        int ci[4] = {0x7fffffff, 0x7fffffff, 0x7fffffff, 0x7fffffff};
#pragma unroll 4
        for (int e = 0; e < 16; e++) {
            float4 f = red[tid * 16 + e];
            ins4(cv, ci, f.x, __float_as_int(f.y));
            ins4(cv, ci, f.z, __float_as_int(f.w));
        }
        *(int4*)(g_cand + (size_t)(mtile * MT + tid) * 8 + hf * 4) =
            make_int4(ci[0], ci[1], ci[2], ci[3]);
    }
}

/* ---------- K2: exact fp32 rescore of 8 candidates + gather + loss ---------- */
__global__ void rescore_gather_kernel(const float* __restrict__ z,
                                      const float* __restrict__ cb,
                                      float* __restrict__ out) {
    const int lane = threadIdx.x & 31, warp = threadIdx.x >> 5;
    const int row = blockIdx.x * 8 + warp;
    __shared__ float wsum[8];
    __shared__ float sred[256];
    __shared__ int s_last;

    const int4 c0 = *(const int4*)(g_cand + (size_t)row * 8);
    const int4 c1 = *(const int4*)(g_cand + (size_t)row * 8 + 4);
    const int cand[8] = {c0.x, c0.y, c0.z, c0.w, c1.x, c1.y, c1.z, c1.w};
    const float4* z4 = (const float4*)(z + (size_t)row * DIM);
    const float4 a0 = z4[lane], a1 = z4[lane + 32];
    float d[8];
#pragma unroll
    for (int q = 0; q < 8; q++) {
        const float4* e4 = (const float4*)(cb + (size_t)cand[q] * DIM);
        float4 b0 = e4[lane], b1 = e4[lane + 32];
        d[q] = a0.x * b0.x + a0.y * b0.y + a0.z * b0.z + a0.w * b0.w
             + a1.x * b1.x + a1.y * b1.y + a1.z * b1.z + a1.w * b1.w;
    }
#pragma unroll
    for (int o = 16; o > 0; o >>= 1)
#pragma unroll
        for (int q = 0; q < 8; q++) d[q] += __shfl_xor_sync(0xffffffffu, d[q], o);

    float bv = CUDART_INF_F; int bi = 0x7fffffff;
#pragma unroll
    for (int q = 0; q < 8; q++) {
        float dist = fmaf(-2.f, d[q], __ldg(&g_codenorm[cand[q]]));
        if (dist < bv || (dist == bv && cand[q] < bi)) { bv = dist; bi = cand[q]; }
    }

    const float4* e4 = (const float4*)(cb + (size_t)bi * DIM);
    float* out_ze = out + (size_t)row * DIM;
    float* out_zq = out + (size_t)NROWS * DIM + 1 + (size_t)row * DIM;
    float s = 0.f;
#pragma unroll
    for (int l = 0; l < 2; l++) {
        int f = lane + 32 * l;
        float4 ze = (l == 0) ? a0 : a1;
        float4 zq = e4[f];
        *(float4*)(out_ze + f * 4) = ze;
        out_zq[f * 4 + 0] = zq.x; out_zq[f * 4 + 1] = zq.y;
        out_zq[f * 4 + 2] = zq.z; out_zq[f * 4 + 3] = zq.w;
        float dx = zq.x - ze.x, dy = zq.y - ze.y, dz = zq.z - ze.z, dw = zq.w - ze.w;
        s += dx * dx + dy * dy + dz * dz + dw * dw;
    }
#pragma unroll
    for (int o = 16; o > 0; o >>= 1) s += __shfl_down_sync(0xffffffffu, s, o);
    if (lane == 0) wsum[warp] = s;
    __syncthreads();
    if (threadIdx.x == 0) {
        float t = 0.f;
#pragma unroll
        for (int wv = 0; wv < 8; wv++) t += wsum[wv];
        g_losspart[blockIdx.x] = t;
        __threadfence();
        unsigned r = atomicAdd(&g_ctr, 1u);
        s_last = (r == NPART - 1) ? 1 : 0;
    }
    __syncthreads();
    if (s_last) {  /* last block: deterministic fixed-order final reduce */
        float t = 0.f;
        for (int i = threadIdx.x; i < NPART; i += 256) t += g_losspart[i];
        sred[threadIdx.x] = t;
        __syncthreads();
        for (int o = 128; o > 0; o >>= 1) {
            if (threadIdx.x < o) sred[threadIdx.x] += sred[threadIdx.x + o];
            __syncthreads();
        }
        if (threadIdx.x == 0)
            out[(size_t)NROWS * DIM] = 2.f * sred[0] / (float)((size_t)NROWS * DIM);
    }
}

extern "C" void kernel_launch(void* const* d_in, const int* in_sizes, int n_in,
                              void* d_out, int out_size) {
    const float* z  = (const float*)d_in[0];
    const float* cb = (const float*)d_in[1];
    float* out = (float*)d_out;

    cudaFuncSetAttribute(vq_mma_kernel, cudaFuncAttributeMaxDynamicSharedMemorySize, GEMM_SMEM);

    split_z_kernel<<<NROWS * 32 / 256, 256>>>(z);
    split_cb_kernel<<<KCB * 32 / 256, 256>>>(cb);
    codenorm_kernel<<<KCB / 8, 256>>>(cb);
    vq_mma_kernel<<<dim3(NHALFS, MTILES), 256, GEMM_SMEM>>>();
    rescore_gather_kernel<<<NPART, 256>>>(z, cb, out);
}

// round 12
// speedup vs baseline: 1.2921x; 1.2921x over previous
#include <cuda_runtime.h>
#include <cuda_fp16.h>
#include <math_constants.h>
#include <cstdint>

#define NROWS 16384
#define DIM   256
#define KCB   8192
#define MT    64                 /* m rows per CTA          */
#define MTILES (NROWS / MT)      /* 256 m-tiles             */
#define NHALFS 2                 /* N split across CTAs     */
#define CODES_HALF (KCB / NHALFS)
#define NT_CTA (CODES_HALF / 128)/* 32 n-tiles per CTA      */
#define NSTAGE (NT_CTA * 4)      /* 128 k64 stages per CTA  */
#define NPART (NROWS / 8)

/* GEMM smem layout (dynamic) — 65KB total => 3 CTAs/SM */
#define SA_OFF  0                /* A fp16: 64 rows x 512B = 32KB      */
#define SB_OFF  32768            /* 2 x 16KB B stage double buffer     */
#define SCN_OFF 65536            /* 2 x 512B codenorm tiles            */
#define GEMM_SMEM 66560

/* ------------- device globals (no allocs allowed) ------------- */
__device__ unsigned char g_zt[MTILES * 32768];            /* 8MB pre-swizzled A fp16       */
__device__ unsigned char g_cbt[NHALFS * NSTAGE * 16384];  /* 4MB pre-swizzled B fp16 stages*/
__device__ float g_codenorm[KCB];
__device__ int   g_cand[NROWS * 8];
__device__ float g_losspart[NPART];
__device__ unsigned g_ctr;

/* ------------- helpers ------------- */
__device__ __forceinline__ unsigned smem_u32(const void* p) {
    unsigned a;
    asm("{ .reg .u64 t; cvta.to.shared.u64 t, %1; cvt.u32.u64 %0, t; }" : "=r"(a) : "l"(p));
    return a;
}
__device__ __forceinline__ void cp_async16(unsigned dst, const void* src) {
    asm volatile("cp.async.cg.shared.global [%0], [%1], 16;" :: "r"(dst), "l"(src) : "memory");
}
/* volatile is load-bearing: without it the compiler may hoist/CSE these smem
   reads across cp.async.wait_group/__syncthreads into the wrong buffer epoch */
__device__ __forceinline__ void ldsm_x4(unsigned* r, unsigned addr) {
    asm volatile("ldmatrix.sync.aligned.m8n8.x4.shared.b16 {%0,%1,%2,%3}, [%4];"
                 : "=r"(r[0]), "=r"(r[1]), "=r"(r[2]), "=r"(r[3]) : "r"(addr));
}
__device__ __forceinline__ void mma16816(float (&c)[4], const unsigned* a, unsigned b0, unsigned b1) {
    asm volatile("mma.sync.aligned.m16n8k16.row.col.f32.f16.f16.f32 "
                 "{%0,%1,%2,%3}, {%4,%5,%6,%7}, {%8,%9}, {%0,%1,%2,%3};"
                 : "+f"(c[0]), "+f"(c[1]), "+f"(c[2]), "+f"(c[3])
                 : "r"(a[0]), "r"(a[1]), "r"(a[2]), "r"(a[3]), "r"(b0), "r"(b1));
}
/* top-2 with both indices packed into one reg (codes < 8192 fit in 16 bits) */
__device__ __forceinline__ void top2p(float& v1, float& v2, unsigned& ti, float d, unsigned c) {
    if (d < v2) {
        if (d < v1) { v2 = v1; ti = (ti << 16) | c; v1 = d; }
        else        { v2 = d;  ti = (ti & 0xFFFFu) | (c << 16); }
    }
}
__device__ __forceinline__ void ins4(float (&cv)[4], int (&ci)[4], float v, int i) {
#pragma unroll
    for (int j = 0; j < 4; j++) {
        bool lt = (v < cv[j]) || (v == cv[j] && i < ci[j]);
        float tv = lt ? cv[j] : v; int ti = lt ? ci[j] : i;
        if (lt) { cv[j] = v; ci[j] = i; }
        v = tv; i = ti;
    }
}

/* ---------- preprocess: z -> swizzled fp16 tiles (64 rows x 512B, full k) ---------- */
__global__ void split_z_kernel(const float* __restrict__ z) {
    const int id = blockIdx.x * 256 + threadIdx.x;   /* 0..524287 */
    const int row = id >> 5;
    const int j = id & 31;                           /* 16B chunk (8 fp16) along k */
    const float* src = z + (size_t)row * DIM + j * 8;
    float4 f0 = __ldg((const float4*)src);
    float4 f1 = __ldg((const float4*)(src + 4));
    float v[8] = {f0.x, f0.y, f0.z, f0.w, f1.x, f1.y, f1.z, f1.w};
    unsigned short hv[8];
#pragma unroll
    for (int e = 0; e < 8; e++) hv[e] = __half_as_ushort(__float2half_rn(v[e]));
    size_t base = (size_t)(row >> 6) * 32768 + (size_t)(row & 63) * 512 + ((j ^ (row & 7)) << 4);
    *(uint4*)(g_zt + base) = *(uint4*)hv;
}

/* ---------- preprocess: codebook -> n-major swizzled fp16 k64 stages ---------- */
__global__ void split_cb_kernel(const float* __restrict__ cb) {
    const int id = blockIdx.x * 256 + threadIdx.x;   /* 0..262143 */
    const int n = id >> 5;                           /* code row 0..8191 */
    const int j = id & 31;                           /* 16B chunk over full k256 */
    const float* src = cb + (size_t)n * DIM + j * 8;
    float4 f0 = __ldg((const float4*)src);
    float4 f1 = __ldg((const float4*)(src + 4));
    float v[8] = {f0.x, f0.y, f0.z, f0.w, f1.x, f1.y, f1.z, f1.w};
    unsigned short hv[8];
#pragma unroll
    for (int e = 0; e < 8; e++) hv[e] = __half_as_ushort(__float2half_rn(v[e]));
    const int q = j >> 3, kb = j & 7;                /* k64 quarter, chunk within */
    const int hf = n >> 12, nt = (n >> 7) & 31, nr = n & 127;
    size_t base = ((size_t)(hf * NSTAGE + nt * 4 + q)) * 16384
                + (size_t)nr * 128 + ((kb ^ (nr & 7)) << 4);
    *(uint4*)(g_cbt + base) = *(uint4*)hv;
}

/* ---------- exact fp32 codebook norms ---------- */
__global__ void codenorm_kernel(const float* __restrict__ cb) {
    int warp = threadIdx.x >> 5, lane = threadIdx.x & 31;
    int row = blockIdx.x * 8 + warp;
    const float4* c4 = (const float4*)(cb + (size_t)row * DIM);
    float s = 0.f;
#pragma unroll
    for (int l = 0; l < 2; l++) {
        float4 v = c4[lane + 32 * l];
        s += v.x * v.x + v.y * v.y + v.z * v.z + v.w * v.w;
    }
#pragma unroll
    for (int o = 16; o > 0; o >>= 1) s += __shfl_down_sync(0xffffffffu, s, o);
    if (lane == 0) g_codenorm[row] = s;
}

/* ---------- stage producer: 16KB into buffer (s&1) (+ cn tile on quarter 0), 128 thr ---------- */
__device__ __forceinline__ void issue_stage(unsigned smb, int s, int hf, int tid) {
    const unsigned char* src = g_cbt + ((size_t)(hf * NSTAGE + s)) * 16384 + tid * 16;
    unsigned dst = smb + SB_OFF + (s & 1) * 16384 + tid * 16;
#pragma unroll
    for (int i = 0; i < 8; i++) cp_async16(dst + i * 2048, src + (size_t)i * 2048);
    if ((s & 3) == 0 && tid < 32)
        cp_async16(smb + SCN_OFF + ((s >> 2) & 1) * 512 + tid * 16,
                   (const unsigned char*)g_codenorm + (size_t)hf * 16384 + (size_t)(s >> 2) * 512 + tid * 16);
    asm volatile("cp.async.commit_group;" ::: "memory");
}

/* ---------- compute one k64 quarter: 4 k16-steps, warp tile 64m x 32n ---------- */
template<int Q, int BUF>
__device__ __forceinline__ void compute_quarter(float (&acc)[4][4][4], unsigned smb,
                                                int wn, int lane) {
    const int lm = lane & 15;
    const int sel = lane >> 4;
    const int xa = lm & 7;
    unsigned abase[4];
#pragma unroll
    for (int mi = 0; mi < 4; mi++)
        abase[mi] = smb + SA_OFF + (mi * 16 + lm) * 512 + Q * 128;
    const unsigned bb = smb + SB_OFF + BUF * 16384 + (wn * 32 + lm) * 128;
    const unsigned b1off = 16 * 128;
#pragma unroll
    for (int ks = 0; ks < 4; ks++) {
        const unsigned off = (unsigned)(((ks * 2 + sel) ^ xa) << 4);
        unsigned a[4][4], b[2][4];
#pragma unroll
        for (int mi = 0; mi < 4; mi++) ldsm_x4(a[mi], abase[mi] + off);
        ldsm_x4(b[0], bb + off);
        ldsm_x4(b[1], bb + b1off + off);
#pragma unroll
        for (int mi = 0; mi < 4; mi++) {
            mma16816(acc[mi][0], a[mi], b[0][0], b[0][2]);
            mma16816(acc[mi][1], a[mi], b[0][1], b[0][3]);
            mma16816(acc[mi][2], a[mi], b[1][0], b[1][2]);
            mma16816(acc[mi][3], a[mi], b[1][1], b[1][3]);
        }
    }
}

#define WAIT_SYNC() do { \
    asm volatile("cp.async.wait_group 0;" ::: "memory"); \
    __syncthreads(); \
} while (0)

/* ---------- K1: fp16 tensor GEMM (64m x 4096n per CTA) + fused top-2 argmin ---------- */
__global__ void __launch_bounds__(128, 3) vq_mma_kernel() {
    extern __shared__ __align__(128) unsigned char smem[];
    const unsigned smb = smem_u32(smem);
    const int tid = threadIdx.x;
    const int lane = tid & 31;
    const int wn = tid >> 5;                 /* 4 warps, each owns 32 n-cols */
    const int hf = blockIdx.x;               /* N half            */
    const int mtile = blockIdx.y;            /* 64-row m tile     */

    if (hf == 0 && mtile == 0 && tid == 0) g_ctr = 0;

    { /* prologue group: resident A (32KB) + stage 0 + cn tile 0 */
        const unsigned char* src = g_zt + (size_t)mtile * 32768 + tid * 16;
        unsigned dst = smb + SA_OFF + tid * 16;
#pragma unroll
        for (int i = 0; i < 16; i++) cp_async16(dst + i * 2048, src + (size_t)i * 2048);
        issue_stage(smb, 0, hf, tid);
    }

    float acc[4][4][4];
#pragma unroll
    for (int i = 0; i < 4; i++)
#pragma unroll
        for (int j = 0; j < 4; j++)
#pragma unroll
            for (int r = 0; r < 4; r++) acc[i][j][r] = 0.f;
    float tv1[8], tv2[8];
    unsigned tip[8];
#pragma unroll
    for (int sl = 0; sl < 8; sl++) { tv1[sl] = CUDART_INF_F; tv2[sl] = CUDART_INF_F; tip[sl] = 0; }

    const int colb = wn * 32 + 2 * (lane & 3);
    for (int nt = 0; nt < NT_CTA; nt++) {
        const int s0 = nt * 4;
        WAIT_SYNC(); issue_stage(smb, s0 + 1, hf, tid);
        compute_quarter<0, 0>(acc, smb, wn, lane);
        WAIT_SYNC(); issue_stage(smb, s0 + 2, hf, tid);
        compute_quarter<1, 1>(acc, smb, wn, lane);
        WAIT_SYNC(); issue_stage(smb, s0 + 3, hf, tid);
        compute_quarter<2, 0>(acc, smb, wn, lane);
        WAIT_SYNC();
        if (nt + 1 < NT_CTA) issue_stage(smb, s0 + 4, hf, tid);
        compute_quarter<3, 1>(acc, smb, wn, lane);
        { /* epilogue: dist + packed top-2, zero acc */
            const float* cnp = (const float*)(smem + SCN_OFF + (nt & 1) * 512);
            const unsigned cbase = (unsigned)(hf * CODES_HALF + nt * 128 + colb);
#pragma unroll
            for (int ni = 0; ni < 4; ni++) {
                float cn0 = cnp[colb + ni * 8];
                float cn1 = cnp[colb + ni * 8 + 1];
                unsigned c0 = cbase + ni * 8;
#pragma unroll
                for (int mi = 0; mi < 4; mi++) {
#pragma unroll
                    for (int h = 0; h < 2; h++) {
                        int sl = mi * 2 + h;
                        float d0 = fmaf(-2.f, acc[mi][ni][h * 2],     cn0);
                        float d1 = fmaf(-2.f, acc[mi][ni][h * 2 + 1], cn1);
                        top2p(tv1[sl], tv2[sl], tip[sl], d0, c0);
                        top2p(tv1[sl], tv2[sl], tip[sl], d1, c0 + 1);
                        acc[mi][ni][h * 2] = 0.f;
                        acc[mi][ni][h * 2 + 1] = 0.f;
                    }
                }
            }
        }
    }

    /* dump all 32 per-row candidates, then per-row top-4 merge */
    __syncthreads();
    float4* red = (float4*)(smem + SB_OFF);    /* 64 rows x 16 entries x 16B = 16KB */
#pragma unroll
    for (int sl = 0; sl < 8; sl++) {
        int mi = sl >> 1, h = sl & 1;
        int row = mi * 16 + h * 8 + (lane >> 2);
        red[row * 16 + wn * 4 + (lane & 3)] =
            make_float4(tv1[sl], __int_as_float((int)(tip[sl] & 0xFFFFu)),
                        tv2[sl], __int_as_float((int)(tip[sl] >> 16)));
    }
    __syncthreads();
    if (tid < 64) {
        float cv[4] = {CUDART_INF_F, CUDART_INF_F, CUDART_INF_F, CUDART_INF_F};
        int ci[4] = {0x7fffffff, 0x7fffffff, 0x7fffffff, 0x7fffffff};
#pragma unroll 4
        for (int e = 0; e < 16; e++) {
            float4 f = red[tid * 16 + e];
            ins4(cv, ci, f.x, __float_as_int(f.y));
            ins4(cv, ci, f.z, __float_as_int(f.w));
        }
        *(int4*)(g_cand + (size_t)(mtile * MT + tid) * 8 + hf * 4) =
            make_int4(ci[0], ci[1], ci[2], ci[3]);
    }
}

/* ---------- K2: exact fp32 rescore of 8 candidates + gather + loss ---------- */
__global__ void rescore_gather_kernel(const float* __restrict__ z,
                                      const float* __restrict__ cb,
                                      float* __restrict__ out) {
    const int lane = threadIdx.x & 31, warp = threadIdx.x >> 5;
    const int row = blockIdx.x * 8 + warp;
    __shared__ float wsum[8];
    __shared__ float sred[256];
    __shared__ int s_last;

    const int4 c0 = *(const int4*)(g_cand + (size_t)row * 8);
    const int4 c1 = *(const int4*)(g_cand + (size_t)row * 8 + 4);
    const int cand[8] = {c0.x, c0.y, c0.z, c0.w, c1.x, c1.y, c1.z, c1.w};
    const float4* z4 = (const float4*)(z + (size_t)row * DIM);
    const float4 a0 = z4[lane], a1 = z4[lane + 32];
    float d[8];
#pragma unroll
    for (int q = 0; q < 8; q++) {
        const float4* e4 = (const float4*)(cb + (size_t)cand[q] * DIM);
        float4 b0 = e4[lane], b1 = e4[lane + 32];
        d[q] = a0.x * b0.x + a0.y * b0.y + a0.z * b0.z + a0.w * b0.w
             + a1.x * b1.x + a1.y * b1.y + a1.z * b1.z + a1.w * b1.w;
    }
#pragma unroll
    for (int o = 16; o > 0; o >>= 1)
#pragma unroll
        for (int q = 0; q < 8; q++) d[q] += __shfl_xor_sync(0xffffffffu, d[q], o);

    float bv = CUDART_INF_F; int bi = 0x7fffffff;
#pragma unroll
    for (int q = 0; q < 8; q++) {
        float dist = fmaf(-2.f, d[q], __ldg(&g_codenorm[cand[q]]));
        if (dist < bv || (dist == bv && cand[q] < bi)) { bv = dist; bi = cand[q]; }
    }

    const float4* e4 = (const float4*)(cb + (size_t)bi * DIM);
    float* out_ze = out + (size_t)row * DIM;
    float* out_zq = out + (size_t)NROWS * DIM + 1 + (size_t)row * DIM;
    float s = 0.f;
#pragma unroll
    for (int l = 0; l < 2; l++) {
        int f = lane + 32 * l;
        float4 ze = (l == 0) ? a0 : a1;
        float4 zq = e4[f];
        *(float4*)(out_ze + f * 4) = ze;
        out_zq[f * 4 + 0] = zq.x; out_zq[f * 4 + 1] = zq.y;
        out_zq[f * 4 + 2] = zq.z; out_zq[f * 4 + 3] = zq.w;
        float dx = zq.x - ze.x, dy = zq.y - ze.y, dz = zq.z - ze.z, dw = zq.w - ze.w;
        s += dx * dx + dy * dy + dz * dz + dw * dw;
    }
#pragma unroll
    for (int o = 16; o > 0; o >>= 1) s += __shfl_down_sync(0xffffffffu, s, o);
    if (lane == 0) wsum[warp] = s;
    __syncthreads();
    if (threadIdx.x == 0) {
        float t = 0.f;
#pragma unroll
        for (int wv = 0; wv < 8; wv++) t += wsum[wv];
        g_losspart[blockIdx.x] = t;
        __threadfence();
        unsigned r = atomicAdd(&g_ctr, 1u);
        s_last = (r == NPART - 1) ? 1 : 0;
    }
    __syncthreads();
    if (s_last) {  /* last block: deterministic fixed-order final reduce */
        float t = 0.f;
        for (int i = threadIdx.x; i < NPART; i += 256) t += g_losspart[i];
        sred[threadIdx.x] = t;
        __syncthreads();
        for (int o = 128; o > 0; o >>= 1) {
            if (threadIdx.x < o) sred[threadIdx.x] += sred[threadIdx.x + o];
            __syncthreads();
        }
        if (threadIdx.x == 0)
            out[(size_t)NROWS * DIM] = 2.f * sred[0] / (float)((size_t)NROWS * DIM);
    }
}

extern "C" void kernel_launch(void* const* d_in, const int* in_sizes, int n_in,
                              void* d_out, int out_size) {
    const float* z  = (const float*)d_in[0];
    const float* cb = (const float*)d_in[1];
    float* out = (float*)d_out;

    cudaFuncSetAttribute(vq_mma_kernel, cudaFuncAttributeMaxDynamicSharedMemorySize, GEMM_SMEM);

    split_z_kernel<<<NROWS * 32 / 256, 256>>>(z);
    split_cb_kernel<<<KCB * 32 / 256, 256>>>(cb);
    codenorm_kernel<<<KCB / 8, 256>>>(cb);
    vq_mma_kernel<<<dim3(NHALFS, MTILES), 128, GEMM_SMEM>>>();
    rescore_gather_kernel<<<NPART, 256>>>(z, cb, out);
}

// round 13
// speedup vs baseline: 1.3695x; 1.0599x over previous
#include <cuda_runtime.h>
#include <math_constants.h>
#include <cstdint>

#define NROWS 16384
#define DIM   256
#define KCB   8192
#define MT    64                 /* rows per CTA            */
#define MTILES (NROWS / MT)      /* 256 CTAs                */
#define NTILES (KCB / 128)       /* 64 code tiles           */
#define NSTAGE (2 * NTILES)      /* 128 k128x128n stages    */
#define NPART (NROWS / 8)

/* GEMM smem layout (dynamic) */
#define SA_OFF  0                /* A fp8: 64 rows x 256B = 16KB        */
#define SB_OFF  16384            /* 2 x 16KB B stage double buffer      */
#define SCN_OFF 49152            /* 2 x 512B codenorm tiles             */
#define GEMM_SMEM 50176

/* ------------- device globals (no allocs allowed) ------------- */
__device__ unsigned char g_zt[MTILES * 16384];       /* 4MB pre-swizzled A fp8  */
__device__ unsigned char g_cbt[NSTAGE * 16384];      /* 2MB pre-swizzled B fp8  */
__device__ float g_codenorm[KCB];
__device__ int   g_cand[NROWS * 8];
__device__ float g_losspart[NPART];
__device__ unsigned g_ctr;

/* ------------- helpers ------------- */
__device__ __forceinline__ unsigned smem_u32(const void* p) {
    unsigned a;
    asm("{ .reg .u64 t; cvta.to.shared.u64 t, %1; cvt.u32.u64 %0, t; }" : "=r"(a) : "l"(p));
    return a;
}
__device__ __forceinline__ void cp_async16(unsigned dst, const void* src) {
    asm volatile("cp.async.cg.shared.global [%0], [%1], 16;" :: "r"(dst), "l"(src) : "memory");
}
/* volatile is load-bearing: keeps smem reads inside their buffer epoch */
__device__ __forceinline__ void ldsm_x4(unsigned* r, unsigned addr) {
    asm volatile("ldmatrix.sync.aligned.m8n8.x4.shared.b16 {%0,%1,%2,%3}, [%4];"
                 : "=r"(r[0]), "=r"(r[1]), "=r"(r[2]), "=r"(r[3]) : "r"(addr));
}
__device__ __forceinline__ void mma16832(float (&c)[4], const unsigned* a, unsigned b0, unsigned b1) {
    asm volatile("mma.sync.aligned.m16n8k32.row.col.f32.e4m3.e4m3.f32 "
                 "{%0,%1,%2,%3}, {%4,%5,%6,%7}, {%8,%9}, {%0,%1,%2,%3};"
                 : "+f"(c[0]), "+f"(c[1]), "+f"(c[2]), "+f"(c[3])
                 : "r"(a[0]), "r"(a[1]), "r"(a[2]), "r"(a[3]), "r"(b0), "r"(b1));
}
/* pack 2 floats into 2 e4m3 bytes (same convention for A and B -> order cancels in dot) */
__device__ __forceinline__ unsigned short cvt2_e4m3(float lo, float hi) {
    unsigned short r;
    asm("cvt.rn.satfinite.e4m3x2.f32 %0, %1, %2;" : "=h"(r) : "f"(hi), "f"(lo));
    return r;
}
__device__ __forceinline__ void top3_update(float& v1, int& i1, float& v2, int& i2,
                                            float& v3, int& i3, float d, int c) {
    if (d < v3) {
        if (d < v2) {
            v3 = v2; i3 = i2;
            if (d < v1) { v2 = v1; i2 = i1; v1 = d; i1 = c; }
            else        { v2 = d;  i2 = c; }
        } else { v3 = d; i3 = c; }
    }
}
__device__ __forceinline__ void ins8(float (&cv)[8], int (&ci)[8], float v, int i) {
#pragma unroll
    for (int j = 0; j < 8; j++) {
        bool lt = (v < cv[j]) || (v == cv[j] && i < ci[j]);
        float tv = lt ? cv[j] : v; int ti = lt ? ci[j] : i;
        if (lt) { cv[j] = v; ci[j] = i; }
        v = tv; i = ti;
    }
}

/* ---------- preprocess: z -> swizzled fp8 A tiles (64 rows x 256B) ---------- */
__global__ void split_z_kernel(const float* __restrict__ z) {
    const int id = blockIdx.x * 256 + threadIdx.x;   /* 0..262143 */
    const int row = id >> 4, kb = id & 15;           /* 16B block along k */
    const float4* s = (const float4*)(z + (size_t)row * DIM + kb * 16);
    float4 f[4] = {__ldg(s), __ldg(s + 1), __ldg(s + 2), __ldg(s + 3)};
    const float* v = (const float*)f;
    unsigned short h[8];
#pragma unroll
    for (int e = 0; e < 8; e++) h[e] = cvt2_e4m3(v[2 * e], v[2 * e + 1]);
    size_t dst = (size_t)(row >> 6) * 16384 + (size_t)(row & 63) * 256 + ((kb ^ (row & 7)) << 4);
    *(uint4*)(g_zt + dst) = *(uint4*)h;
}

/* ---------- preprocess: codebook -> n-major swizzled fp8 stages (128n x 128B) ---------- */
__global__ void split_cb_kernel(const float* __restrict__ cb) {
    const int id = blockIdx.x * 256 + threadIdx.x;   /* 0..131071 */
    const int n = id >> 4, kb16 = id & 15;
    const float4* s = (const float4*)(cb + (size_t)n * DIM + kb16 * 16);
    float4 f[4] = {__ldg(s), __ldg(s + 1), __ldg(s + 2), __ldg(s + 3)};
    const float* v = (const float*)f;
    unsigned short h[8];
#pragma unroll
    for (int e = 0; e < 8; e++) h[e] = cvt2_e4m3(v[2 * e], v[2 * e + 1]);
    const int kb = kb16 & 7, hh = kb16 >> 3;         /* chunk within k128, k-half */
    size_t dst = ((size_t)(n >> 7) * 2 + hh) * 16384
               + (size_t)(n & 127) * 128 + ((kb ^ (n & 7)) << 4);
    *(uint4*)(g_cbt + dst) = *(uint4*)h;
}

/* ---------- exact fp32 codebook norms ---------- */
__global__ void codenorm_kernel(const float* __restrict__ cb) {
    int warp = threadIdx.x >> 5, lane = threadIdx.x & 31;
    int row = blockIdx.x * 8 + warp;
    const float4* c4 = (const float4*)(cb + (size_t)row * DIM);
    float s = 0.f;
#pragma unroll
    for (int l = 0; l < 2; l++) {
        float4 v = c4[lane + 32 * l];
        s += v.x * v.x + v.y * v.y + v.z * v.z + v.w * v.w;
    }
#pragma unroll
    for (int o = 16; o > 0; o >>= 1) s += __shfl_down_sync(0xffffffffu, s, o);
    if (lane == 0) g_codenorm[row] = s;
}

/* ---------- stage producer: 16KB into buffer (s&1) (+ cn tile on even stage) ---------- */
__device__ __forceinline__ void issue_stage(unsigned smb, int s, int tid) {
    const unsigned char* src = g_cbt + (size_t)s * 16384 + tid * 16;
    unsigned dst = smb + SB_OFF + (s & 1) * 16384 + tid * 16;
#pragma unroll
    for (int i = 0; i < 4; i++) cp_async16(dst + i * 4096, src + (size_t)i * 4096);
    if ((s & 1) == 0 && tid < 32)
        cp_async16(smb + SCN_OFF + ((s >> 1) & 1) * 512 + tid * 16,
                   (const unsigned char*)g_codenorm + (size_t)(s >> 1) * 512 + tid * 16);
    asm volatile("cp.async.commit_group;" ::: "memory");
}

/* ---------- compute one k128 stage: 4 k32-steps, warp tile 32m x 32n, buf = H ---------- */
template<int H>
__device__ __forceinline__ void compute_stage(float (&acc)[2][4][4], unsigned smb,
                                              int wm, int wn, int lane) {
    const int lm = lane & 15;
    const int sel = lane >> 4;
    const int mlo = wm * 32 + lm, mhi = mlo + 16;
    const unsigned aL = smb + SA_OFF + mlo * 256;
    const unsigned aH = smb + SA_OFF + mhi * 256;
    const int xlo = mlo & 7, xhi = mhi & 7;
    const int nn = wn * 32 + lm;
    const int xb = nn & 7;                       /* (nn+16)&7 == nn&7 */
    const unsigned b0a = smb + SB_OFF + H * 16384 + nn * 128;
    const unsigned b1a = b0a + 16 * 128;
#pragma unroll
    for (int s = 0; s < 4; s++) {
        const int kA = H * 8 + 2 * s + sel;      /* 16B block in A row (0..15) */
        const int kB = 2 * s + sel;              /* 16B block in B row (0..7)  */
        unsigned a0[4], a1[4], b0[4], b1[4];
        ldsm_x4(a0, aL + ((kA ^ xlo) << 4));
        ldsm_x4(a1, aH + ((kA ^ xhi) << 4));
        ldsm_x4(b0, b0a + ((kB ^ xb) << 4));
        ldsm_x4(b1, b1a + ((kB ^ xb) << 4));
        /* b pairing (validated R7): (r0,r2)=n-lo (k0-15,k16-31), (r1,r3)=n-hi */
        mma16832(acc[0][0], a0, b0[0], b0[2]);
        mma16832(acc[0][1], a0, b0[1], b0[3]);
        mma16832(acc[0][2], a0, b1[0], b1[2]);
        mma16832(acc[0][3], a0, b1[1], b1[3]);
        mma16832(acc[1][0], a1, b0[0], b0[2]);
        mma16832(acc[1][1], a1, b0[1], b0[3]);
        mma16832(acc[1][2], a1, b1[0], b1[2]);
        mma16832(acc[1][3], a1, b1[1], b1[3]);
    }
}

#define WAIT_SYNC() do { \
    asm volatile("cp.async.wait_group 0;" ::: "memory"); \
    __syncthreads(); \
} while (0)

/* ---------- K1: fp8 tensor GEMM + fused top-3/thread argmin ---------- */
__global__ void __launch_bounds__(256, 2) vq_mma_kernel() {
    extern __shared__ __align__(128) unsigned char smem[];
    const unsigned smb = smem_u32(smem);
    const int tid = threadIdx.x;
    const int lane = tid & 31;
    const int w = tid >> 5;
    const int wm = w >> 2, wn = w & 3;       /* 2m x 4n warp grid */
    const int mtile = blockIdx.x;

    if (mtile == 0 && tid == 0) g_ctr = 0;

    { /* prologue group: resident A (16KB) + stage 0 + cn tile 0 */
        const unsigned char* src = g_zt + (size_t)mtile * 16384 + tid * 16;
        unsigned dst = smb + SA_OFF + tid * 16;
#pragma unroll
        for (int i = 0; i < 4; i++) cp_async16(dst + i * 4096, src + (size_t)i * 4096);
        issue_stage(smb, 0, tid);
    }

    float acc[2][4][4];
#pragma unroll
    for (int i = 0; i < 2; i++)
#pragma unroll
        for (int j = 0; j < 4; j++)
#pragma unroll
            for (int r = 0; r < 4; r++) acc[i][j][r] = 0.f;
    float tv1[4], tv2[4], tv3[4];
    int ti1[4], ti2[4], ti3[4];
#pragma unroll
    for (int sl = 0; sl < 4; sl++) {
        tv1[sl] = CUDART_INF_F; tv2[sl] = CUDART_INF_F; tv3[sl] = CUDART_INF_F;
        ti1[sl] = 0x7fffffff; ti2[sl] = 0x7fffffff; ti3[sl] = 0x7fffffff;
    }

    const int colb = wn * 32 + 2 * (lane & 3);
    for (int ii = 0; ii < NTILES; ii++) {
        /* ---- stage 0 of tile ii (k 0-127) ---- */
        WAIT_SYNC();
        issue_stage(smb, 2 * ii + 1, tid);
        compute_stage<0>(acc, smb, wm, wn, lane);
        /* ---- stage 1 of tile ii (k 128-255) ---- */
        WAIT_SYNC();
        if (2 * ii + 2 < NSTAGE) issue_stage(smb, 2 * ii + 2, tid);
        compute_stage<1>(acc, smb, wm, wn, lane);
        { /* epilogue: dist + top-3, zero acc */
            const float* cnp = (const float*)(smem + SCN_OFF + (ii & 1) * 512);
#pragma unroll
            for (int ni = 0; ni < 4; ni++) {
                float cn0 = cnp[colb + ni * 8];
                float cn1 = cnp[colb + ni * 8 + 1];
                int c0 = ii * 128 + colb + ni * 8;
#pragma unroll
                for (int mi = 0; mi < 2; mi++) {
#pragma unroll
                    for (int h = 0; h < 2; h++) {
                        int sl = mi * 2 + h;
                        float d0 = fmaf(-2.f, acc[mi][ni][h * 2],     cn0);
                        float d1 = fmaf(-2.f, acc[mi][ni][h * 2 + 1], cn1);
                        top3_update(tv1[sl], ti1[sl], tv2[sl], ti2[sl], tv3[sl], ti3[sl], d0, c0);
                        top3_update(tv1[sl], ti1[sl], tv2[sl], ti2[sl], tv3[sl], ti3[sl], d1, c0 + 1);
                        acc[mi][ni][h * 2] = 0.f;
                        acc[mi][ni][h * 2 + 1] = 0.f;
                    }
                }
            }
        }
    }

    /* dump 48 per-row candidates, then per-row top-8 merge */
    __syncthreads();
    float2* red = (float2*)(smem + SB_OFF);    /* 64 rows x 48 entries x 8B = 24KB */
    const int t = wn * 4 + (lane & 3);
#pragma unroll
    for (int sl = 0; sl < 4; sl++) {
        int row = wm * 32 + (sl >> 1) * 16 + (sl & 1) * 8 + (lane >> 2);
        float2* p = red + row * 48 + t * 3;
        p[0] = make_float2(tv1[sl], __int_as_float(ti1[sl]));
        p[1] = make_float2(tv2[sl], __int_as_float(ti2[sl]));
        p[2] = make_float2(tv3[sl], __int_as_float(ti3[sl]));
    }
    __syncthreads();
    if (tid < 64) {
        float cv[8]; int ci[8];
#pragma unroll
        for (int j = 0; j < 8; j++) { cv[j] = CUDART_INF_F; ci[j] = 0x7fffffff; }
#pragma unroll 4
        for (int e = 0; e < 48; e++) {
            float2 f = red[tid * 48 + e];
            ins8(cv, ci, f.x, __float_as_int(f.y));
        }
        int* dst = g_cand + (size_t)(mtile * MT + tid) * 8;
        *(int4*)dst       = make_int4(ci[0], ci[1], ci[2], ci[3]);
        *(int4*)(dst + 4) = make_int4(ci[4], ci[5], ci[6], ci[7]);
    }
}

/* ---------- K2: exact fp32 rescore of top-8 + gather + loss (last block finalizes) ---------- */
__global__ void rescore_gather_kernel(const float* __restrict__ z,
                                      const float* __restrict__ cb,
                                      float* __restrict__ out) {
    const int lane = threadIdx.x & 31, warp = threadIdx.x >> 5;
    const int row = blockIdx.x * 8 + warp;
    __shared__ float wsum[8];
    __shared__ float sred[256];
    __shared__ int s_last;

    const int4 c0 = *(const int4*)(g_cand + (size_t)row * 8);
    const int4 c1 = *(const int4*)(g_cand + (size_t)row * 8 + 4);
    const int cand[8] = {c0.x, c0.y, c0.z, c0.w, c1.x, c1.y, c1.z, c1.w};
    const float4* z4 = (const float4*)(z + (size_t)row * DIM);
    const float4 a0 = z4[lane], a1 = z4[lane + 32];
    float d[8];
#pragma unroll
    for (int q = 0; q < 8; q++) {
        const float4* e4 = (const float4*)(cb + (size_t)cand[q] * DIM);
        float4 b0 = e4[lane], b1 = e4[lane + 32];
        d[q] = a0.x * b0.x + a0.y * b0.y + a0.z * b0.z + a0.w * b0.w
             + a1.x * b1.x + a1.y * b1.y + a1.z * b1.z + a1.w * b1.w;
    }
#pragma unroll
    for (int o = 16; o > 0; o >>= 1)
#pragma unroll
        for (int q = 0; q < 8; q++) d[q] += __shfl_xor_sync(0xffffffffu, d[q], o);

    float bv = CUDART_INF_F; int bi = 0x7fffffff;
#pragma unroll
    for (int q = 0; q < 8; q++) {
        float dist = fmaf(-2.f, d[q], __ldg(&g_codenorm[cand[q]]));
        if (dist < bv || (dist == bv && cand[q] < bi)) { bv = dist; bi = cand[q]; }
    }

    const float4* e4 = (const float4*)(cb + (size_t)bi * DIM);
    float* out_ze = out + (size_t)row * DIM;
    float* out_zq = out + (size_t)NROWS * DIM + 1 + (size_t)row * DIM;
    float s = 0.f;
#pragma unroll
    for (int l = 0; l < 2; l++) {
        int f = lane + 32 * l;
        float4 ze = (l == 0) ? a0 : a1;
        float4 zq = e4[f];
        *(float4*)(out_ze + f * 4) = ze;
        out_zq[f * 4 + 0] = zq.x; out_zq[f * 4 + 1] = zq.y;
        out_zq[f * 4 + 2] = zq.z; out_zq[f * 4 + 3] = zq.w;
        float dx = zq.x - ze.x, dy = zq.y - ze.y, dz = zq.z - ze.z, dw = zq.w - ze.w;
        s += dx * dx + dy * dy + dz * dz + dw * dw;
    }
#pragma unroll
    for (int o = 16; o > 0; o >>= 1) s += __shfl_down_sync(0xffffffffu, s, o);
    if (lane == 0) wsum[warp] = s;
    __syncthreads();
    if (threadIdx.x == 0) {
        float t = 0.f;
#pragma unroll
        for (int wv = 0; wv < 8; wv++) t += wsum[wv];
        g_losspart[blockIdx.x] = t;
        __threadfence();
        unsigned r = atomicAdd(&g_ctr, 1u);
        s_last = (r == NPART - 1) ? 1 : 0;
    }
    __syncthreads();
    if (s_last) {  /* last block: deterministic fixed-order final reduce */
        float t = 0.f;
        for (int i = threadIdx.x; i < NPART; i += 256) t += g_losspart[i];
        sred[threadIdx.x] = t;
        __syncthreads();
        for (int o = 128; o > 0; o >>= 1) {
            if (threadIdx.x < o) sred[threadIdx.x] += sred[threadIdx.x + o];
            __syncthreads();
        }
        if (threadIdx.x == 0)
            out[(size_t)NROWS * DIM] = 2.f * sred[0] / (float)((size_t)NROWS * DIM);
    }
}

extern "C" void kernel_launch(void* const* d_in, const int* in_sizes, int n_in,
                              void* d_out, int out_size) {
    const float* z  = (const float*)d_in[0];
    const float* cb = (const float*)d_in[1];
    float* out = (float*)d_out;

    cudaFuncSetAttribute(vq_mma_kernel, cudaFuncAttributeMaxDynamicSharedMemorySize, GEMM_SMEM);

    split_z_kernel<<<NROWS * 16 / 256, 256>>>(z);
    split_cb_kernel<<<KCB * 16 / 256, 256>>>(cb);
    codenorm_kernel<<<KCB / 8, 256>>>(cb);
    vq_mma_kernel<<<MTILES, 256, GEMM_SMEM>>>();
    rescore_gather_kernel<<<NPART, 256>>>(z, cb, out);
}

// round 14
// speedup vs baseline: 1.6371x; 1.1954x over previous
#include <cuda_runtime.h>
#include <cuda_fp16.h>
#include <math_constants.h>
#include <cstdint>

#define NROWS 16384
#define DIM   256
#define KCB   8192
#define MT    64                 /* rows per CTA           */
#define MTILES (NROWS / MT)      /* 256 CTAs               */
#define NTILES (KCB / 128)       /* 64 code tiles          */
#define NHALF  (2 * NTILES)      /* 128 k128xn128 halves   */
#define NPART (NROWS / 8)

/* fused preprocess block ranges */
#define PZ_BLKS  2048            /* split_z   */
#define PC_BLKS  128             /* split_cb  */
#define PN_BLKS  1024            /* codenorm  */

/* GEMM smem layout (dynamic) */
#define SA_OFF  0                /* A fp16: 4 sub-chunks x 8KB = 32768 */
#define SB_OFF  32768            /* 2 x 32KB B half double buffer      */
#define SCN_OFF 98304            /* 2 x 512B codenorm tiles            */
#define GEMM_SMEM 99328

/* ------------- device globals (no allocs allowed) ------------- */
__device__ unsigned char g_zt[MTILES * 32768];       /* 8MB pre-swizzled A fp16       */
__device__ unsigned char g_cbt[NHALF * 32768];       /* 4MB pre-swizzled B fp16 halves*/
__device__ float g_codenorm[KCB];
__device__ int   g_cand[NROWS * 4];
__device__ float g_losspart[NPART];
__device__ unsigned g_ctr;

/* ------------- helpers ------------- */
__device__ __forceinline__ unsigned smem_u32(const void* p) {
    unsigned a;
    asm("{ .reg .u64 t; cvta.to.shared.u64 t, %1; cvt.u32.u64 %0, t; }" : "=r"(a) : "l"(p));
    return a;
}
__device__ __forceinline__ void cp_async16(unsigned dst, const void* src) {
    asm volatile("cp.async.cg.shared.global [%0], [%1], 16;" :: "r"(dst), "l"(src) : "memory");
}
/* volatile is load-bearing: keeps smem reads inside their buffer epoch */
__device__ __forceinline__ void ldsm_x4(unsigned* r, unsigned addr) {
    asm volatile("ldmatrix.sync.aligned.m8n8.x4.shared.b16 {%0,%1,%2,%3}, [%4];"
                 : "=r"(r[0]), "=r"(r[1]), "=r"(r[2]), "=r"(r[3]) : "r"(addr));
}
__device__ __forceinline__ void ldsm_x4_t(unsigned* r, unsigned addr) {
    asm volatile("ldmatrix.sync.aligned.m8n8.x4.trans.shared.b16 {%0,%1,%2,%3}, [%4];"
                 : "=r"(r[0]), "=r"(r[1]), "=r"(r[2]), "=r"(r[3]) : "r"(addr));
}
__device__ __forceinline__ void mma16816(float (&c)[4], const unsigned* a, unsigned b0, unsigned b1) {
    asm volatile("mma.sync.aligned.m16n8k16.row.col.f32.f16.f16.f32 "
                 "{%0,%1,%2,%3}, {%4,%5,%6,%7}, {%8,%9}, {%0,%1,%2,%3};"
                 : "+f"(c[0]), "+f"(c[1]), "+f"(c[2]), "+f"(c[3])
                 : "r"(a[0]), "r"(a[1]), "r"(a[2]), "r"(a[3]), "r"(b0), "r"(b1));
}
__device__ __forceinline__ void top2_update(float& v1, int& i1, float& v2, int& i2, float d, int c) {
    if (d < v2) {
        if (d < v1) { v2 = v1; i2 = i1; v1 = d; i1 = c; }
        else        { v2 = d;  i2 = c; }
    }
}
__device__ __forceinline__ void ins4(float (&cv)[4], int (&ci)[4], float v, int i) {
#pragma unroll
    for (int j = 0; j < 4; j++) {
        bool lt = (v < cv[j]) || (v == cv[j] && i < ci[j]);
        float tv = lt ? cv[j] : v; int ti = lt ? ci[j] : i;
        if (lt) { cv[j] = v; ci[j] = i; }
        v = tv; i = ti;
    }
}

/* ---------- K0 (fused preprocess): split_z | split_cb | codenorm by block range ---------- */
__global__ void preprocess_kernel(const float* __restrict__ z, const float* __restrict__ cb) {
    __shared__ __half sh[128][136];   /* used only by split_cb blocks */
    const int bid = blockIdx.x;
    const int tid = threadIdx.x;

    if (bid < PZ_BLKS) {
        /* ---- split_z: z -> swizzled fp16 tiles (64 rows x 4 k64 sub-chunks) ---- */
        const int id = bid * 256 + tid;
        const int row = id >> 5;
        const int j = id & 31;
        const float* src = z + (size_t)row * DIM + j * 8;
        float4 f0 = __ldg((const float4*)src);
        float4 f1 = __ldg((const float4*)(src + 4));
        float v[8] = {f0.x, f0.y, f0.z, f0.w, f1.x, f1.y, f1.z, f1.w};
        unsigned short hv[8];
#pragma unroll
        for (int e = 0; e < 8; e++) hv[e] = __half_as_ushort(__float2half_rn(v[e]));
        const int m = row & 63;
        const int kc = j >> 3, c = j & 7;
        size_t base = (size_t)(row >> 6) * 32768 + (size_t)kc * 8192 + m * 128 + ((c ^ (m & 7)) << 4);
        *(uint4*)(g_zt + base) = *(uint4*)hv;
    } else if (bid < PZ_BLKS + PC_BLKS) {
        /* ---- split_cb: codebook -> k-major swizzled fp16 32KB halves ---- */
        const int hidx = bid - PZ_BLKS;        /* 0..127 */
        const int nt = hidx >> 1, h = hidx & 1;
        const int n = tid >> 1, khalf = (tid & 1) * 64;
        const float* src = cb + (size_t)(nt * 128 + n) * DIM + h * 128 + khalf;
#pragma unroll
        for (int j = 0; j < 16; j++) {
            float4 f = __ldg((const float4*)(src + j * 4));
            sh[khalf + j * 4 + 0][n] = __float2half_rn(f.x);
            sh[khalf + j * 4 + 1][n] = __float2half_rn(f.y);
            sh[khalf + j * 4 + 2][n] = __float2half_rn(f.z);
            sh[khalf + j * 4 + 3][n] = __float2half_rn(f.w);
        }
        __syncthreads();
        unsigned char* dst = g_cbt + (size_t)hidx * 32768;
#pragma unroll
        for (int j = 0; j < 8; j++) {
            int u = tid + j * 256;              /* 0..2047 */
            int k = u >> 4, c = u & 15;
            uint4 v = *(const uint4*)(&sh[k][c * 8]);
            *(uint4*)(dst + (size_t)k * 256 + ((c ^ (k & 7)) << 4)) = v;
        }
    } else {
        /* ---- codenorm: exact fp32 ||e||^2, one warp per row ---- */
        const int warp = tid >> 5, lane = tid & 31;
        const int row = (bid - PZ_BLKS - PC_BLKS) * 8 + warp;
        const float4* c4 = (const float4*)(cb + (size_t)row * DIM);
        float s = 0.f;
#pragma unroll
        for (int l = 0; l < 2; l++) {
            float4 v = c4[lane + 32 * l];
            s += v.x * v.x + v.y * v.y + v.z * v.z + v.w * v.w;
        }
#pragma unroll
        for (int o = 16; o > 0; o >>= 1) s += __shfl_down_sync(0xffffffffu, s, o);
        if (lane == 0) g_codenorm[row] = s;
    }
}

/* ---------- B-half producer: 32KB into buffer (s&1), one commit group ---------- */
__device__ __forceinline__ void issue_half(unsigned smb, int s, int tid) {
    const unsigned char* src = g_cbt + (size_t)s * 32768 + tid * 16;
    unsigned dst = smb + SB_OFF + (s & 1) * 32768 + tid * 16;
#pragma unroll
    for (int i = 0; i < 8; i++) cp_async16(dst + i * 4096, src + (size_t)i * 4096);
    if ((s & 1) == 0 && tid < 32)
        cp_async16(smb + SCN_OFF + ((s >> 1) & 1) * 512 + tid * 16,
                   (const unsigned char*)g_codenorm + (size_t)(s >> 1) * 512 + tid * 16);
    asm volatile("cp.async.commit_group;" ::: "memory");
}

/* ---------- compute one k128 half: 8 k16-steps, warp tile 32m x 32n, buf = H ---------- */
template<int H>
__device__ __forceinline__ void compute_half(float (&acc)[2][4][4], unsigned smb,
                                             int wm, int wn, int lane) {
    const int mlo = wm * 32 + (lane & 15);
    const int mhi = mlo + 16;
    const int klane = lane & 15;
    const int sel = lane >> 4;
    const unsigned alo_base = smb + SA_OFF + mlo * 128;
    const unsigned ahi_base = smb + SA_OFF + mhi * 128;
    const int xlo = mlo & 7, xhi = mhi & 7;
    const int cb0 = wn * 4 + sel;
    const unsigned bb = smb + SB_OFF + H * 32768 + klane * 256;
    const unsigned b0base = bb + (((cb0)     ^ (klane & 7)) << 4);
    const unsigned b1base = bb + (((cb0 + 2) ^ (klane & 7)) << 4);
#pragma unroll
    for (int ks = 0; ks < 8; ks++) {
        const int base_g = H * 16 + ks * 2;        /* compile-time, even */
        const int sub = base_g >> 3;               /* compile-time       */
        unsigned a0[4], a1[4], b0[4], b1[4];
        {
            int kc = (base_g & 7) + sel;           /* stays within 0..7  */
            ldsm_x4(a0, alo_base + sub * 8192 + ((kc ^ xlo) << 4));
            ldsm_x4(a1, ahi_base + sub * 8192 + ((kc ^ xhi) << 4));
        }
        ldsm_x4_t(b0, b0base + ks * 4096);
        ldsm_x4_t(b1, b1base + ks * 4096);
        mma16816(acc[0][0], a0, b0[0], b0[1]);
        mma16816(acc[0][1], a0, b0[2], b0[3]);
        mma16816(acc[0][2], a0, b1[0], b1[1]);
        mma16816(acc[0][3], a0, b1[2], b1[3]);
        mma16816(acc[1][0], a1, b0[0], b0[1]);
        mma16816(acc[1][1], a1, b0[2], b0[3]);
        mma16816(acc[1][2], a1, b1[0], b1[1]);
        mma16816(acc[1][3], a1, b1[2], b1[3]);
    }
}

/* ---------- K1: fp16 tensor GEMM + fused top-2/thread argmin ---------- */
__global__ void __launch_bounds__(256, 2) vq_mma_kernel() {
    extern __shared__ __align__(128) unsigned char smem[];
    const unsigned smb = smem_u32(smem);
    const int tid = threadIdx.x;
    const int lane = tid & 31;
    const int w = tid >> 5;
    const int wm = w >> 2, wn = w & 3;
    const int mtile = blockIdx.x;

    if (mtile == 0 && tid == 0) g_ctr = 0;   /* reset rescore completion counter */

    { /* prologue group: resident A (32KB) + half 0 + cn tile 0 */
        const unsigned char* src = g_zt + (size_t)mtile * 32768 + tid * 16;
        unsigned dst = smb + SA_OFF + tid * 16;
#pragma unroll
        for (int i = 0; i < 8; i++) cp_async16(dst + i * 4096, src + (size_t)i * 4096);
        issue_half(smb, 0, tid);   /* commits A + half0 + cn0 as one group */
    }

    float acc[2][4][4];
#pragma unroll
    for (int i = 0; i < 2; i++)
#pragma unroll
        for (int j = 0; j < 4; j++)
#pragma unroll
            for (int r = 0; r < 4; r++) acc[i][j][r] = 0.f;
    float tv1[4], tv2[4];
    int ti1[4], ti2[4];
#pragma unroll
    for (int sl = 0; sl < 4; sl++) { tv1[sl] = CUDART_INF_F; tv2[sl] = CUDART_INF_F; ti1[sl] = 0; ti2[sl] = 0; }

    const int colb = wn * 32 + 2 * (lane & 3);
    for (int ii = 0; ii < NTILES; ii++) {
        /* ---- half 0 of tile ii ---- */
        asm volatile("cp.async.wait_group 0;" ::: "memory");
        __syncthreads();
        issue_half(smb, 2 * ii + 1, tid);
        compute_half<0>(acc, smb, wm, wn, lane);
        /* ---- half 1 of tile ii ---- */
        asm volatile("cp.async.wait_group 0;" ::: "memory");
        __syncthreads();
        if (2 * ii + 2 < NHALF) issue_half(smb, 2 * ii + 2, tid);
        compute_half<1>(acc, smb, wm, wn, lane);
        { /* epilogue: dist + top-2, zero acc */
            const float* cnp = (const float*)(smem + SCN_OFF + (ii & 1) * 512);
#pragma unroll
            for (int ni = 0; ni < 4; ni++) {
                float cn0 = cnp[colb + ni * 8];
                float cn1 = cnp[colb + ni * 8 + 1];
                int c0 = ii * 128 + colb + ni * 8;
#pragma unroll
                for (int mi = 0; mi < 2; mi++) {
#pragma unroll
                    for (int h = 0; h < 2; h++) {
                        int sl = mi * 2 + h;
                        float d0 = fmaf(-2.f, acc[mi][ni][h * 2],     cn0);
                        float d1 = fmaf(-2.f, acc[mi][ni][h * 2 + 1], cn1);
                        top2_update(tv1[sl], ti1[sl], tv2[sl], ti2[sl], d0, c0);
                        top2_update(tv1[sl], ti1[sl], tv2[sl], ti2[sl], d1, c0 + 1);
                        acc[mi][ni][h * 2] = 0.f;
                        acc[mi][ni][h * 2 + 1] = 0.f;
                    }
                }
            }
        }
    }

    /* dump all 32 per-row candidates, then per-row top-4 merge */
    __syncthreads();
    float4* red = (float4*)(smem + SB_OFF);    /* 64 rows x 16 entries x 16B */
#pragma unroll
    for (int sl = 0; sl < 4; sl++) {
        int row = wm * 32 + (sl >> 1) * 16 + (sl & 1) * 8 + (lane >> 2);
        red[row * 16 + wn * 4 + (lane & 3)] =
            make_float4(tv1[sl], __int_as_float(ti1[sl]), tv2[sl], __int_as_float(ti2[sl]));
    }
    __syncthreads();
    if (tid < 64) {
        float cv[4] = {CUDART_INF_F, CUDART_INF_F, CUDART_INF_F, CUDART_INF_F};
        int ci[4] = {0x7fffffff, 0x7fffffff, 0x7fffffff, 0x7fffffff};
#pragma unroll
        for (int e = 0; e < 16; e++) {
            float4 f = red[tid * 16 + e];
            ins4(cv, ci, f.x, __float_as_int(f.y));
            ins4(cv, ci, f.z, __float_as_int(f.w));
        }
        *(int4*)(g_cand + (size_t)(mtile * MT + tid) * 4) = make_int4(ci[0], ci[1], ci[2], ci[3]);
    }
}

/* ---------- K2: exact fp32 rescore of top-4 + gather + loss (last block finalizes) ---------- */
__global__ void rescore_gather_kernel(const float* __restrict__ z,
                                      const float* __restrict__ cb,
                                      float* __restrict__ out) {
    const int lane = threadIdx.x & 31, warp = threadIdx.x >> 5;
    const int row = blockIdx.x * 8 + warp;
    __shared__ float wsum[8];
    __shared__ float sred[256];
    __shared__ int s_last;

    const int4 cc = *(const int4*)(g_cand + (size_t)row * 4);
    const int cand[4] = {cc.x, cc.y, cc.z, cc.w};
    const float4* z4 = (const float4*)(z + (size_t)row * DIM);
    float4 a[2], b[4][2];
    float d[4] = {0.f, 0.f, 0.f, 0.f};
#pragma unroll
    for (int l = 0; l < 2; l++) {
        int f = lane + 32 * l;
        a[l] = z4[f];
#pragma unroll
        for (int q = 0; q < 4; q++) {
            b[q][l] = ((const float4*)(cb + (size_t)cand[q] * DIM))[f];
            d[q] += a[l].x * b[q][l].x + a[l].y * b[q][l].y
                  + a[l].z * b[q][l].z + a[l].w * b[q][l].w;
        }
    }
#pragma unroll
    for (int o = 16; o > 0; o >>= 1)
#pragma unroll
        for (int q = 0; q < 4; q++) d[q] += __shfl_xor_sync(0xffffffffu, d[q], o);

    float bv = CUDART_INF_F; int bq = 0, bi = 0x7fffffff;
#pragma unroll
    for (int q = 0; q < 4; q++) {
        float dist = fmaf(-2.f, d[q], __ldg(&g_codenorm[cand[q]]));
        if (dist < bv || (dist == bv && cand[q] < bi)) { bv = dist; bi = cand[q]; bq = q; }
    }

    float* out_ze = out + (size_t)row * DIM;
    float* out_zq = out + (size_t)NROWS * DIM + 1 + (size_t)row * DIM;
    float s = 0.f;
#pragma unroll
    for (int l = 0; l < 2; l++) {
        int f = lane + 32 * l;
        float4 ze = a[l];
        float4 zq = b[bq][l];
        *(float4*)(out_ze + f * 4) = ze;
        out_zq[f * 4 + 0] = zq.x; out_zq[f * 4 + 1] = zq.y;
        out_zq[f * 4 + 2] = zq.z; out_zq[f * 4 + 3] = zq.w;
        float dx = zq.x - ze.x, dy = zq.y - ze.y, dz = zq.z - ze.z, dw = zq.w - ze.w;
        s += dx * dx + dy * dy + dz * dz + dw * dw;
    }
#pragma unroll
    for (int o = 16; o > 0; o >>= 1) s += __shfl_down_sync(0xffffffffu, s, o);
    if (lane == 0) wsum[warp] = s;
    __syncthreads();
    if (threadIdx.x == 0) {
        float t = 0.f;
#pragma unroll
        for (int wv = 0; wv < 8; wv++) t += wsum[wv];
        g_losspart[blockIdx.x] = t;
        __threadfence();
        unsigned r = atomicAdd(&g_ctr, 1u);
        s_last = (r == NPART - 1) ? 1 : 0;
    }
    __syncthreads();
    if (s_last) {  /* last block: deterministic fixed-order final reduce */
        float t = 0.f;
        for (int i = threadIdx.x; i < NPART; i += 256) t += g_losspart[i];
        sred[threadIdx.x] = t;
        __syncthreads();
        for (int o = 128; o > 0; o >>= 1) {
            if (threadIdx.x < o) sred[threadIdx.x] += sred[threadIdx.x + o];
            __syncthreads();
        }
        if (threadIdx.x == 0)
            out[(size_t)NROWS * DIM] = 2.f * sred[0] / (float)((size_t)NROWS * DIM);
    }
}

extern "C" void kernel_launch(void* const* d_in, const int* in_sizes, int n_in,
                              void* d_out, int out_size) {
    const float* z  = (const float*)d_in[0];
    const float* cb = (const float*)d_in[1];
    float* out = (float*)d_out;

    cudaFuncSetAttribute(vq_mma_kernel, cudaFuncAttributeMaxDynamicSharedMemorySize, GEMM_SMEM);

    preprocess_kernel<<<PZ_BLKS + PC_BLKS + PN_BLKS, 256>>>(z, cb);
    vq_mma_kernel<<<MTILES, 256, GEMM_SMEM>>>();
    rescore_gather_kernel<<<NPART, 256>>>(z, cb, out);
}

// round 15
// speedup vs baseline: 1.6884x; 1.0313x over previous
#include <cuda_runtime.h>
#include <cuda_fp16.h>
#include <math_constants.h>
#include <cstdint>

#define NROWS 16384
#define DIM   256
#define KCB   8192
#define MT    64                 /* rows per CTA           */
#define MTILES (NROWS / MT)      /* 256 CTAs               */
#define NTILES (KCB / 128)       /* 64 code tiles          */
#define NHALF  (2 * NTILES)      /* 128 k128xn128 halves   */
#define NPART (NROWS / 8)

/* fused preprocess block ranges */
#define PZ_BLKS  2048            /* split_z + out_ze copy */
#define PC_BLKS  128             /* split_cb (smem-free)  */
#define PN_BLKS  1024            /* codenorm              */

/* GEMM smem layout (dynamic) */
#define SA_OFF  0                /* A fp16: 4 sub-chunks x 8KB = 32768 */
#define SB_OFF  32768            /* 2 x 32KB B half double buffer      */
#define SCN_OFF 98304            /* 2 x 512B codenorm tiles            */
#define GEMM_SMEM 99328

/* ------------- device globals (no allocs allowed) ------------- */
__device__ unsigned char g_zt[MTILES * 32768];       /* 8MB pre-swizzled A fp16       */
__device__ unsigned char g_cbt[NHALF * 32768];       /* 4MB pre-swizzled B fp16 halves*/
__device__ float g_codenorm[KCB];
__device__ int   g_cand[NROWS * 4];
__device__ float g_losspart[NPART];
__device__ unsigned g_ctr;

/* ------------- helpers ------------- */
__device__ __forceinline__ unsigned smem_u32(const void* p) {
    unsigned a;
    asm("{ .reg .u64 t; cvta.to.shared.u64 t, %1; cvt.u32.u64 %0, t; }" : "=r"(a) : "l"(p));
    return a;
}
__device__ __forceinline__ void cp_async16(unsigned dst, const void* src) {
    asm volatile("cp.async.cg.shared.global [%0], [%1], 16;" :: "r"(dst), "l"(src) : "memory");
}
/* volatile is load-bearing: keeps smem reads inside their buffer epoch */
__device__ __forceinline__ void ldsm_x4(unsigned* r, unsigned addr) {
    asm volatile("ldmatrix.sync.aligned.m8n8.x4.shared.b16 {%0,%1,%2,%3}, [%4];"
                 : "=r"(r[0]), "=r"(r[1]), "=r"(r[2]), "=r"(r[3]) : "r"(addr));
}
__device__ __forceinline__ void ldsm_x4_t(unsigned* r, unsigned addr) {
    asm volatile("ldmatrix.sync.aligned.m8n8.x4.trans.shared.b16 {%0,%1,%2,%3}, [%4];"
                 : "=r"(r[0]), "=r"(r[1]), "=r"(r[2]), "=r"(r[3]) : "r"(addr));
}
__device__ __forceinline__ void mma16816(float (&c)[4], const unsigned* a, unsigned b0, unsigned b1) {
    asm volatile("mma.sync.aligned.m16n8k16.row.col.f32.f16.f16.f32 "
                 "{%0,%1,%2,%3}, {%4,%5,%6,%7}, {%8,%9}, {%0,%1,%2,%3};"
                 : "+f"(c[0]), "+f"(c[1]), "+f"(c[2]), "+f"(c[3])
                 : "r"(a[0]), "r"(a[1]), "r"(a[2]), "r"(a[3]), "r"(b0), "r"(b1));
}
__device__ __forceinline__ void top2_update(float& v1, int& i1, float& v2, int& i2, float d, int c) {
    if (d < v2) {
        if (d < v1) { v2 = v1; i2 = i1; v1 = d; i1 = c; }
        else        { v2 = d;  i2 = c; }
    }
}
__device__ __forceinline__ void ins4(float (&cv)[4], int (&ci)[4], float v, int i) {
#pragma unroll
    for (int j = 0; j < 4; j++) {
        bool lt = (v < cv[j]) || (v == cv[j] && i < ci[j]);
        float tv = lt ? cv[j] : v; int ti = lt ? ci[j] : i;
        if (lt) { cv[j] = v; ci[j] = i; }
        v = tv; i = ti;
    }
}

/* ---------- K0 (fused preprocess, smem-free): split_z | split_cb | codenorm ---------- */
__global__ void preprocess_kernel(const float* __restrict__ z, const float* __restrict__ cb,
                                  float* __restrict__ out) {
    const int bid = blockIdx.x;
    const int tid = threadIdx.x;

    if (bid < PZ_BLKS) {
        /* ---- split_z: z -> swizzled fp16 tiles + out_ze copy ---- */
        const int id = bid * 256 + tid;
        const int row = id >> 5;
        const int j = id & 31;
        const float* src = z + (size_t)row * DIM + j * 8;
        float4 f0 = __ldg((const float4*)src);
        float4 f1 = __ldg((const float4*)(src + 4));
        /* out_ze copy rides along (z already in registers) */
        *(float4*)(out + (size_t)row * DIM + j * 8)     = f0;
        *(float4*)(out + (size_t)row * DIM + j * 8 + 4) = f1;
        float v[8] = {f0.x, f0.y, f0.z, f0.w, f1.x, f1.y, f1.z, f1.w};
        unsigned short hv[8];
#pragma unroll
        for (int e = 0; e < 8; e++) hv[e] = __half_as_ushort(__float2half_rn(v[e]));
        const int m = row & 63;
        const int kc = j >> 3, c = j & 7;
        size_t base = (size_t)(row >> 6) * 32768 + (size_t)kc * 8192 + m * 128 + ((c ^ (m & 7)) << 4);
        *(uint4*)(g_zt + base) = *(uint4*)hv;
    } else if (bid < PZ_BLKS + PC_BLKS) {
        /* ---- split_cb: register-only 8x8 transpose, no smem ---- */
        const int hidx = bid - PZ_BLKS;        /* 0..127 */
        const int nt = hidx >> 1, h = hidx & 1;
        const int bn = tid & 15, bk = tid >> 4;
        const float* src = cb + (size_t)(nt * 128 + bn * 8) * DIM + h * 128 + bk * 8;
        unsigned char* dst = g_cbt + (size_t)hidx * 32768;
        unsigned short hv[8][8];               /* [kk][r] */
#pragma unroll
        for (int r = 0; r < 8; r++) {
            float4 f0 = __ldg((const float4*)(src + (size_t)r * DIM));
            float4 f1 = __ldg((const float4*)(src + (size_t)r * DIM + 4));
            hv[0][r] = __half_as_ushort(__float2half_rn(f0.x));
            hv[1][r] = __half_as_ushort(__float2half_rn(f0.y));
            hv[2][r] = __half_as_ushort(__float2half_rn(f0.z));
            hv[3][r] = __half_as_ushort(__float2half_rn(f0.w));
            hv[4][r] = __half_as_ushort(__float2half_rn(f1.x));
            hv[5][r] = __half_as_ushort(__float2half_rn(f1.y));
            hv[6][r] = __half_as_ushort(__float2half_rn(f1.z));
            hv[7][r] = __half_as_ushort(__float2half_rn(f1.w));
        }
#pragma unroll
        for (int kk = 0; kk < 8; kk++) {
            int k = bk * 8 + kk;
            *(uint4*)(dst + (size_t)k * 256 + ((bn ^ (k & 7)) << 4)) = *(uint4*)hv[kk];
        }
    } else {
        /* ---- codenorm: exact fp32 ||e||^2, one warp per row ---- */
        const int warp = tid >> 5, lane = tid & 31;
        const int row = (bid - PZ_BLKS - PC_BLKS) * 8 + warp;
        const float4* c4 = (const float4*)(cb + (size_t)row * DIM);
        float s = 0.f;
#pragma unroll
        for (int l = 0; l < 2; l++) {
            float4 v = c4[lane + 32 * l];
            s += v.x * v.x + v.y * v.y + v.z * v.z + v.w * v.w;
        }
#pragma unroll
        for (int o = 16; o > 0; o >>= 1) s += __shfl_down_sync(0xffffffffu, s, o);
        if (lane == 0) g_codenorm[row] = s;
    }
}

/* ---------- B-half producer: 32KB into buffer (s&1), one commit group ---------- */
__device__ __forceinline__ void issue_half(unsigned smb, int s, int tid) {
    const unsigned char* src = g_cbt + (size_t)s * 32768 + tid * 16;
    unsigned dst = smb + SB_OFF + (s & 1) * 32768 + tid * 16;
#pragma unroll
    for (int i = 0; i < 8; i++) cp_async16(dst + i * 4096, src + (size_t)i * 4096);
    if ((s & 1) == 0 && tid < 32)
        cp_async16(smb + SCN_OFF + ((s >> 1) & 1) * 512 + tid * 16,
                   (const unsigned char*)g_codenorm + (size_t)(s >> 1) * 512 + tid * 16);
    asm volatile("cp.async.commit_group;" ::: "memory");
}

/* ---------- compute one k128 half: 8 k16-steps, warp tile 32m x 32n, buf = H ---------- */
template<int H>
__device__ __forceinline__ void compute_half(float (&acc)[2][4][4], unsigned smb,
                                             int wm, int wn, int lane) {
    const int mlo = wm * 32 + (lane & 15);
    const int mhi = mlo + 16;
    const int klane = lane & 15;
    const int sel = lane >> 4;
    const unsigned alo_base = smb + SA_OFF + mlo * 128;
    const unsigned ahi_base = smb + SA_OFF + mhi * 128;
    const int xlo = mlo & 7, xhi = mhi & 7;
    const int cb0 = wn * 4 + sel;
    const unsigned bb = smb + SB_OFF + H * 32768 + klane * 256;
    const unsigned b0base = bb + (((cb0)     ^ (klane & 7)) << 4);
    const unsigned b1base = bb + (((cb0 + 2) ^ (klane & 7)) << 4);
#pragma unroll
    for (int ks = 0; ks < 8; ks++) {
        const int base_g = H * 16 + ks * 2;        /* compile-time, even */
        const int sub = base_g >> 3;               /* compile-time       */
        unsigned a0[4], a1[4], b0[4], b1[4];
        {
            int kc = (base_g & 7) + sel;           /* stays within 0..7  */
            ldsm_x4(a0, alo_base + sub * 8192 + ((kc ^ xlo) << 4));
            ldsm_x4(a1, ahi_base + sub * 8192 + ((kc ^ xhi) << 4));
        }
        ldsm_x4_t(b0, b0base + ks * 4096);
        ldsm_x4_t(b1, b1base + ks * 4096);
        mma16816(acc[0][0], a0, b0[0], b0[1]);
        mma16816(acc[0][1], a0, b0[2], b0[3]);
        mma16816(acc[0][2], a0, b1[0], b1[1]);
        mma16816(acc[0][3], a0, b1[2], b1[3]);
        mma16816(acc[1][0], a1, b0[0], b0[1]);
        mma16816(acc[1][1], a1, b0[2], b0[3]);
        mma16816(acc[1][2], a1, b1[0], b1[1]);
        mma16816(acc[1][3], a1, b1[2], b1[3]);
    }
}

/* ---------- K1: fp16 tensor GEMM + fused top-2/thread argmin ---------- */
__global__ void __launch_bounds__(256, 2) vq_mma_kernel() {
    extern __shared__ __align__(128) unsigned char smem[];
    const unsigned smb = smem_u32(smem);
    const int tid = threadIdx.x;
    const int lane = tid & 31;
    const int w = tid >> 5;
    const int wm = w >> 2, wn = w & 3;
    const int mtile = blockIdx.x;

    if (mtile == 0 && tid == 0) g_ctr = 0;   /* reset rescore completion counter */

    { /* prologue group: resident A (32KB) + half 0 + cn tile 0 */
        const unsigned char* src = g_zt + (size_t)mtile * 32768 + tid * 16;
        unsigned dst = smb + SA_OFF + tid * 16;
#pragma unroll
        for (int i = 0; i < 8; i++) cp_async16(dst + i * 4096, src + (size_t)i * 4096);
        issue_half(smb, 0, tid);   /* commits A + half0 + cn0 as one group */
    }

    float acc[2][4][4];
#pragma unroll
    for (int i = 0; i < 2; i++)
#pragma unroll
        for (int j = 0; j < 4; j++)
#pragma unroll
            for (int r = 0; r < 4; r++) acc[i][j][r] = 0.f;
    float tv1[4], tv2[4];
    int ti1[4], ti2[4];
#pragma unroll
    for (int sl = 0; sl < 4; sl++) { tv1[sl] = CUDART_INF_F; tv2[sl] = CUDART_INF_F; ti1[sl] = 0; ti2[sl] = 0; }

    const int colb = wn * 32 + 2 * (lane & 3);
    for (int ii = 0; ii < NTILES; ii++) {
        /* ---- half 0 of tile ii ---- */
        asm volatile("cp.async.wait_group 0;" ::: "memory");
        __syncthreads();
        issue_half(smb, 2 * ii + 1, tid);
        compute_half<0>(acc, smb, wm, wn, lane);
        /* ---- half 1 of tile ii ---- */
        asm volatile("cp.async.wait_group 0;" ::: "memory");
        __syncthreads();
        if (2 * ii + 2 < NHALF) issue_half(smb, 2 * ii + 2, tid);
        compute_half<1>(acc, smb, wm, wn, lane);
        { /* epilogue: dist + top-2, zero acc */
            const float* cnp = (const float*)(smem + SCN_OFF + (ii & 1) * 512);
#pragma unroll
            for (int ni = 0; ni < 4; ni++) {
                float cn0 = cnp[colb + ni * 8];
                float cn1 = cnp[colb + ni * 8 + 1];
                int c0 = ii * 128 + colb + ni * 8;
#pragma unroll
                for (int mi = 0; mi < 2; mi++) {
#pragma unroll
                    for (int h = 0; h < 2; h++) {
                        int sl = mi * 2 + h;
                        float d0 = fmaf(-2.f, acc[mi][ni][h * 2],     cn0);
                        float d1 = fmaf(-2.f, acc[mi][ni][h * 2 + 1], cn1);
                        top2_update(tv1[sl], ti1[sl], tv2[sl], ti2[sl], d0, c0);
                        top2_update(tv1[sl], ti1[sl], tv2[sl], ti2[sl], d1, c0 + 1);
                        acc[mi][ni][h * 2] = 0.f;
                        acc[mi][ni][h * 2 + 1] = 0.f;
                    }
                }
            }
        }
    }

    /* dump all 32 per-row candidates, then per-row top-4 merge */
    __syncthreads();
    float4* red = (float4*)(smem + SB_OFF);    /* 64 rows x 16 entries x 16B */
#pragma unroll
    for (int sl = 0; sl < 4; sl++) {
        int row = wm * 32 + (sl >> 1) * 16 + (sl & 1) * 8 + (lane >> 2);
        red[row * 16 + wn * 4 + (lane & 3)] =
            make_float4(tv1[sl], __int_as_float(ti1[sl]), tv2[sl], __int_as_float(ti2[sl]));
    }
    __syncthreads();
    if (tid < 64) {
        float cv[4] = {CUDART_INF_F, CUDART_INF_F, CUDART_INF_F, CUDART_INF_F};
        int ci[4] = {0x7fffffff, 0x7fffffff, 0x7fffffff, 0x7fffffff};
#pragma unroll
        for (int e = 0; e < 16; e++) {
            float4 f = red[tid * 16 + e];
            ins4(cv, ci, f.x, __float_as_int(f.y));
            ins4(cv, ci, f.z, __float_as_int(f.w));
        }
        *(int4*)(g_cand + (size_t)(mtile * MT + tid) * 4) = make_int4(ci[0], ci[1], ci[2], ci[3]);
    }
}

/* ---------- K2: exact fp32 rescore of top-4 + gather z_q + loss (last block finalizes) ---------- */
__global__ void rescore_gather_kernel(const float* __restrict__ z,
                                      const float* __restrict__ cb,
                                      float* __restrict__ out) {
    const int lane = threadIdx.x & 31, warp = threadIdx.x >> 5;
    const int row = blockIdx.x * 8 + warp;
    __shared__ float wsum[8];
    __shared__ float sred[256];
    __shared__ int s_last;

    const int4 cc = *(const int4*)(g_cand + (size_t)row * 4);
    const int cand[4] = {cc.x, cc.y, cc.z, cc.w};
    const float4* z4 = (const float4*)(z + (size_t)row * DIM);
    float4 a[2], b[4][2];
    float d[4] = {0.f, 0.f, 0.f, 0.f};
#pragma unroll
    for (int l = 0; l < 2; l++) {
        int f = lane + 32 * l;
        a[l] = z4[f];
#pragma unroll
        for (int q = 0; q < 4; q++) {
            b[q][l] = ((const float4*)(cb + (size_t)cand[q] * DIM))[f];
            d[q] += a[l].x * b[q][l].x + a[l].y * b[q][l].y
                  + a[l].z * b[q][l].z + a[l].w * b[q][l].w;
        }
    }
#pragma unroll
    for (int o = 16; o > 0; o >>= 1)
#pragma unroll
        for (int q = 0; q < 4; q++) d[q] += __shfl_xor_sync(0xffffffffu, d[q], o);

    float bv = CUDART_INF_F; int bq = 0, bi = 0x7fffffff;
#pragma unroll
    for (int q = 0; q < 4; q++) {
        float dist = fmaf(-2.f, d[q], __ldg(&g_codenorm[cand[q]]));
        if (dist < bv || (dist == bv && cand[q] < bi)) { bv = dist; bi = cand[q]; bq = q; }
    }

    /* out_ze already written by preprocess; only z_q + loss here */
    float* out_zq = out + (size_t)NROWS * DIM + 1 + (size_t)row * DIM;
    float s = 0.f;
#pragma unroll
    for (int l = 0; l < 2; l++) {
        int f = lane + 32 * l;
        float4 ze = a[l];
        float4 zq = b[bq][l];
        out_zq[f * 4 + 0] = zq.x; out_zq[f * 4 + 1] = zq.y;
        out_zq[f * 4 + 2] = zq.z; out_zq[f * 4 + 3] = zq.w;
        float dx = zq.x - ze.x, dy = zq.y - ze.y, dz = zq.z - ze.z, dw = zq.w - ze.w;
        s += dx * dx + dy * dy + dz * dz + dw * dw;
    }
#pragma unroll
    for (int o = 16; o > 0; o >>= 1) s += __shfl_down_sync(0xffffffffu, s, o);
    if (lane == 0) wsum[warp] = s;
    __syncthreads();
    if (threadIdx.x == 0) {
        float t = 0.f;
#pragma unroll
        for (int wv = 0; wv < 8; wv++) t += wsum[wv];
        g_losspart[blockIdx.x] = t;
        __threadfence();
        unsigned r = atomicAdd(&g_ctr, 1u);
        s_last = (r == NPART - 1) ? 1 : 0;
    }
    __syncthreads();
    if (s_last) {  /* last block: deterministic fixed-order final reduce */
        float t = 0.f;
        for (int i = threadIdx.x; i < NPART; i += 256) t += g_losspart[i];
        sred[threadIdx.x] = t;
        __syncthreads();
        for (int o = 128; o > 0; o >>= 1) {
            if (threadIdx.x < o) sred[threadIdx.x] += sred[threadIdx.x + o];
            __syncthreads();
        }
        if (threadIdx.x == 0)
            out[(size_t)NROWS * DIM] = 2.f * sred[0] / (float)((size_t)NROWS * DIM);
    }
}

extern "C" void kernel_launch(void* const* d_in, const int* in_sizes, int n_in,
                              void* d_out, int out_size) {
    const float* z  = (const float*)d_in[0];
    const float* cb = (const float*)d_in[1];
    float* out = (float*)d_out;

    cudaFuncSetAttribute(vq_mma_kernel, cudaFuncAttributeMaxDynamicSharedMemorySize, GEMM_SMEM);

    preprocess_kernel<<<PZ_BLKS + PC_BLKS + PN_BLKS, 256>>>(z, cb, out);
    vq_mma_kernel<<<MTILES, 256, GEMM_SMEM>>>();
    rescore_gather_kernel<<<NPART, 256>>>(z, cb, out);
}

// round 16
// speedup vs baseline: 1.7076x; 1.0114x over previous
#include <cuda_runtime.h>
#include <cuda_fp16.h>
#include <math_constants.h>
#include <cstdint>

#define NROWS 16384
#define DIM   256
#define KCB   8192
#define MT    64                 /* rows per CTA           */
#define MTILES (NROWS / MT)      /* 256 CTAs               */
#define NTILES (KCB / 128)       /* 64 code tiles          */
#define NHALF  (2 * NTILES)      /* 128 k128xn128 halves   */
#define NPART (NROWS / 8)

/* preprocess block ranges (cb-side only; A handled by GEMM prologue) */
#define PC_BLKS  128             /* split_cb (smem-free)  */
#define PN_BLKS  1024            /* codenorm              */

/* GEMM smem layout (dynamic) */
#define SA_OFF  0                /* A fp16: 4 sub-chunks x 8KB = 32768 */
#define SB_OFF  32768            /* 2 x 32KB B half double buffer      */
#define SCN_OFF 98304            /* 2 x 512B codenorm tiles            */
#define GEMM_SMEM 99328

/* ------------- device globals (no allocs allowed) ------------- */
__device__ unsigned char g_cbt[NHALF * 32768];       /* 4MB pre-swizzled B fp16 halves*/
__device__ float g_codenorm[KCB];
__device__ int   g_cand[NROWS * 4];
__device__ float g_losspart[NPART];
__device__ unsigned g_ctr;

/* ------------- helpers ------------- */
__device__ __forceinline__ unsigned smem_u32(const void* p) {
    unsigned a;
    asm("{ .reg .u64 t; cvta.to.shared.u64 t, %1; cvt.u32.u64 %0, t; }" : "=r"(a) : "l"(p));
    return a;
}
__device__ __forceinline__ void cp_async16(unsigned dst, const void* src) {
    asm volatile("cp.async.cg.shared.global [%0], [%1], 16;" :: "r"(dst), "l"(src) : "memory");
}
/* volatile is load-bearing: keeps smem reads inside their buffer epoch */
__device__ __forceinline__ void ldsm_x4(unsigned* r, unsigned addr) {
    asm volatile("ldmatrix.sync.aligned.m8n8.x4.shared.b16 {%0,%1,%2,%3}, [%4];"
                 : "=r"(r[0]), "=r"(r[1]), "=r"(r[2]), "=r"(r[3]) : "r"(addr));
}
__device__ __forceinline__ void ldsm_x4_t(unsigned* r, unsigned addr) {
    asm volatile("ldmatrix.sync.aligned.m8n8.x4.trans.shared.b16 {%0,%1,%2,%3}, [%4];"
                 : "=r"(r[0]), "=r"(r[1]), "=r"(r[2]), "=r"(r[3]) : "r"(addr));
}
__device__ __forceinline__ void mma16816(float (&c)[4], const unsigned* a, unsigned b0, unsigned b1) {
    asm volatile("mma.sync.aligned.m16n8k16.row.col.f32.f16.f16.f32 "
                 "{%0,%1,%2,%3}, {%4,%5,%6,%7}, {%8,%9}, {%0,%1,%2,%3};"
                 : "+f"(c[0]), "+f"(c[1]), "+f"(c[2]), "+f"(c[3])
                 : "r"(a[0]), "r"(a[1]), "r"(a[2]), "r"(a[3]), "r"(b0), "r"(b1));
}
__device__ __forceinline__ void top2_update(float& v1, int& i1, float& v2, int& i2, float d, int c) {
    if (d < v2) {
        if (d < v1) { v2 = v1; i2 = i1; v1 = d; i1 = c; }
        else        { v2 = d;  i2 = c; }
    }
}
__device__ __forceinline__ void ins4(float (&cv)[4], int (&ci)[4], float v, int i) {
#pragma unroll
    for (int j = 0; j < 4; j++) {
        bool lt = (v < cv[j]) || (v == cv[j] && i < ci[j]);
        float tv = lt ? cv[j] : v; int ti = lt ? ci[j] : i;
        if (lt) { cv[j] = v; ci[j] = i; }
        v = tv; i = ti;
    }
}

/* ---------- K0 (preprocess, smem-free): split_cb | codenorm ---------- */
__global__ void preprocess_kernel(const float* __restrict__ cb) {
    const int bid = blockIdx.x;
    const int tid = threadIdx.x;

    if (bid < PC_BLKS) {
        /* ---- split_cb: register-only 8x8 transpose, no smem ---- */
        const int hidx = bid;                  /* 0..127 */
        const int nt = hidx >> 1, h = hidx & 1;
        const int bn = tid & 15, bk = tid >> 4;
        const float* src = cb + (size_t)(nt * 128 + bn * 8) * DIM + h * 128 + bk * 8;
        unsigned char* dst = g_cbt + (size_t)hidx * 32768;
        unsigned short hv[8][8];               /* [kk][r] */
#pragma unroll
        for (int r = 0; r < 8; r++) {
            float4 f0 = __ldg((const float4*)(src + (size_t)r * DIM));
            float4 f1 = __ldg((const float4*)(src + (size_t)r * DIM + 4));
            hv[0][r] = __half_as_ushort(__float2half_rn(f0.x));
            hv[1][r] = __half_as_ushort(__float2half_rn(f0.y));
            hv[2][r] = __half_as_ushort(__float2half_rn(f0.z));
            hv[3][r] = __half_as_ushort(__float2half_rn(f0.w));
            hv[4][r] = __half_as_ushort(__float2half_rn(f1.x));
            hv[5][r] = __half_as_ushort(__float2half_rn(f1.y));
            hv[6][r] = __half_as_ushort(__float2half_rn(f1.z));
            hv[7][r] = __half_as_ushort(__float2half_rn(f1.w));
        }
#pragma unroll
        for (int kk = 0; kk < 8; kk++) {
            int k = bk * 8 + kk;
            *(uint4*)(dst + (size_t)k * 256 + ((bn ^ (k & 7)) << 4)) = *(uint4*)hv[kk];
        }
    } else {
        /* ---- codenorm: exact fp32 ||e||^2, one warp per row ---- */
        const int warp = tid >> 5, lane = tid & 31;
        const int row = (bid - PC_BLKS) * 8 + warp;
        const float4* c4 = (const float4*)(cb + (size_t)row * DIM);
        float s = 0.f;
#pragma unroll
        for (int l = 0; l < 2; l++) {
            float4 v = c4[lane + 32 * l];
            s += v.x * v.x + v.y * v.y + v.z * v.z + v.w * v.w;
        }
#pragma unroll
        for (int o = 16; o > 0; o >>= 1) s += __shfl_down_sync(0xffffffffu, s, o);
        if (lane == 0) g_codenorm[row] = s;
    }
}

/* ---------- B-half producer: 32KB into buffer (s&1), one commit group ---------- */
__device__ __forceinline__ void issue_half(unsigned smb, int s, int tid) {
    const unsigned char* src = g_cbt + (size_t)s * 32768 + tid * 16;
    unsigned dst = smb + SB_OFF + (s & 1) * 32768 + tid * 16;
#pragma unroll
    for (int i = 0; i < 8; i++) cp_async16(dst + i * 4096, src + (size_t)i * 4096);
    if ((s & 1) == 0 && tid < 32)
        cp_async16(smb + SCN_OFF + ((s >> 1) & 1) * 512 + tid * 16,
                   (const unsigned char*)g_codenorm + (size_t)(s >> 1) * 512 + tid * 16);
    asm volatile("cp.async.commit_group;" ::: "memory");
}

/* ---------- compute one k128 half: 8 k16-steps, warp tile 32m x 32n, buf = H ---------- */
template<int H>
__device__ __forceinline__ void compute_half(float (&acc)[2][4][4], unsigned smb,
                                             int wm, int wn, int lane) {
    const int mlo = wm * 32 + (lane & 15);
    const int mhi = mlo + 16;
    const int klane = lane & 15;
    const int sel = lane >> 4;
    const unsigned alo_base = smb + SA_OFF + mlo * 128;
    const unsigned ahi_base = smb + SA_OFF + mhi * 128;
    const int xlo = mlo & 7, xhi = mhi & 7;
    const int cb0 = wn * 4 + sel;
    const unsigned bb = smb + SB_OFF + H * 32768 + klane * 256;
    const unsigned b0base = bb + (((cb0)     ^ (klane & 7)) << 4);
    const unsigned b1base = bb + (((cb0 + 2) ^ (klane & 7)) << 4);
#pragma unroll
    for (int ks = 0; ks < 8; ks++) {
        const int base_g = H * 16 + ks * 2;        /* compile-time, even */
        const int sub = base_g >> 3;               /* compile-time       */
        unsigned a0[4], a1[4], b0[4], b1[4];
        {
            int kc = (base_g & 7) + sel;           /* stays within 0..7  */
            ldsm_x4(a0, alo_base + sub * 8192 + ((kc ^ xlo) << 4));
            ldsm_x4(a1, ahi_base + sub * 8192 + ((kc ^ xhi) << 4));
        }
        ldsm_x4_t(b0, b0base + ks * 4096);
        ldsm_x4_t(b1, b1base + ks * 4096);
        mma16816(acc[0][0], a0, b0[0], b0[1]);
        mma16816(acc[0][1], a0, b0[2], b0[3]);
        mma16816(acc[0][2], a0, b1[0], b1[1]);
        mma16816(acc[0][3], a0, b1[2], b1[3]);
        mma16816(acc[1][0], a1, b0[0], b0[1]);
        mma16816(acc[1][1], a1, b0[2], b0[3]);
        mma16816(acc[1][2], a1, b1[0], b1[1]);
        mma16816(acc[1][3], a1, b1[2], b1[3]);
    }
}

/* ---------- K1: fp16 tensor GEMM + fused top-2/thread argmin ----------
   Prologue converts its own A tile from fp32 z (and writes the out_ze copy). */
__global__ void __launch_bounds__(256, 2) vq_mma_kernel(const float* __restrict__ z,
                                                        float* __restrict__ out) {
    extern __shared__ __align__(128) unsigned char smem[];
    const unsigned smb = smem_u32(smem);
    const int tid = threadIdx.x;
    const int lane = tid & 31;
    const int w = tid >> 5;
    const int wm = w >> 2, wn = w & 3;
    const int mtile = blockIdx.x;

    if (mtile == 0 && tid == 0) g_ctr = 0;   /* reset rescore completion counter */

    /* start B half 0 + cn tile 0 first so the A conversion hides under it */
    issue_half(smb, 0, tid);

    { /* prologue: load fp32 A tile, copy to out_ze, convert+swizzle into SA smem */
        const float* zsrc = z + (size_t)mtile * MT * DIM;
        float* oz = out + (size_t)mtile * MT * DIM;
#pragma unroll
        for (int l = 0; l < 8; l++) {
            const int id = l * 256 + tid;       /* 0..2047 */
            const int m = id >> 5, j = id & 31; /* row, 16B k-chunk */
            const float4* s4 = (const float4*)(zsrc + (size_t)m * DIM + j * 8);
            float4 f0 = __ldg(s4), f1 = __ldg(s4 + 1);
            *(float4*)(oz + (size_t)m * DIM + j * 8)     = f0;
            *(float4*)(oz + (size_t)m * DIM + j * 8 + 4) = f1;
            float v[8] = {f0.x, f0.y, f0.z, f0.w, f1.x, f1.y, f1.z, f1.w};
            unsigned short hv[8];
#pragma unroll
            for (int e = 0; e < 8; e++) hv[e] = __half_as_ushort(__float2half_rn(v[e]));
            const int kc = j >> 3, c = j & 7;
            *(uint4*)(smem + SA_OFF + kc * 8192 + m * 128 + ((c ^ (m & 7)) << 4)) = *(uint4*)hv;
        }
    }

    float acc[2][4][4];
#pragma unroll
    for (int i = 0; i < 2; i++)
#pragma unroll
        for (int j = 0; j < 4; j++)
#pragma unroll
            for (int r = 0; r < 4; r++) acc[i][j][r] = 0.f;
    float tv1[4], tv2[4];
    int ti1[4], ti2[4];
#pragma unroll
    for (int sl = 0; sl < 4; sl++) { tv1[sl] = CUDART_INF_F; tv2[sl] = CUDART_INF_F; ti1[sl] = 0; ti2[sl] = 0; }

    const int colb = wn * 32 + 2 * (lane & 3);
    for (int ii = 0; ii < NTILES; ii++) {
        /* ---- half 0 of tile ii ---- */
        asm volatile("cp.async.wait_group 0;" ::: "memory");
        __syncthreads();                        /* also orders prologue STS */
        issue_half(smb, 2 * ii + 1, tid);
        compute_half<0>(acc, smb, wm, wn, lane);
        /* ---- half 1 of tile ii ---- */
        asm volatile("cp.async.wait_group 0;" ::: "memory");
        __syncthreads();
        if (2 * ii + 2 < NHALF) issue_half(smb, 2 * ii + 2, tid);
        compute_half<1>(acc, smb, wm, wn, lane);
        { /* epilogue: dist + top-2, zero acc */
            const float* cnp = (const float*)(smem + SCN_OFF + (ii & 1) * 512);
#pragma unroll
            for (int ni = 0; ni < 4; ni++) {
                float cn0 = cnp[colb + ni * 8];
                float cn1 = cnp[colb + ni * 8 + 1];
                int c0 = ii * 128 + colb + ni * 8;
#pragma unroll
                for (int mi = 0; mi < 2; mi++) {
#pragma unroll
                    for (int h = 0; h < 2; h++) {
                        int sl = mi * 2 + h;
                        float d0 = fmaf(-2.f, acc[mi][ni][h * 2],     cn0);
                        float d1 = fmaf(-2.f, acc[mi][ni][h * 2 + 1], cn1);
                        top2_update(tv1[sl], ti1[sl], tv2[sl], ti2[sl], d0, c0);
                        top2_update(tv1[sl], ti1[sl], tv2[sl], ti2[sl], d1, c0 + 1);
                        acc[mi][ni][h * 2] = 0.f;
                        acc[mi][ni][h * 2 + 1] = 0.f;
                    }
                }
            }
        }
    }

    /* dump all 32 per-row candidates, then per-row top-4 merge */
    __syncthreads();
    float4* red = (float4*)(smem + SB_OFF);    /* 64 rows x 16 entries x 16B */
#pragma unroll
    for (int sl = 0; sl < 4; sl++) {
        int row = wm * 32 + (sl >> 1) * 16 + (sl & 1) * 8 + (lane >> 2);
        red[row * 16 + wn * 4 + (lane & 3)] =
            make_float4(tv1[sl], __int_as_float(ti1[sl]), tv2[sl], __int_as_float(ti2[sl]));
    }
    __syncthreads();
    if (tid < 64) {
        float cv[4] = {CUDART_INF_F, CUDART_INF_F, CUDART_INF_F, CUDART_INF_F};
        int ci[4] = {0x7fffffff, 0x7fffffff, 0x7fffffff, 0x7fffffff};
#pragma unroll
        for (int e = 0; e < 16; e++) {
            float4 f = red[tid * 16 + e];
            ins4(cv, ci, f.x, __float_as_int(f.y));
            ins4(cv, ci, f.z, __float_as_int(f.w));
        }
        *(int4*)(g_cand + (size_t)(mtile * MT + tid) * 4) = make_int4(ci[0], ci[1], ci[2], ci[3]);
    }
}

/* ---------- K2: exact fp32 rescore of top-4 + gather z_q + loss (last block finalizes) ---------- */
__global__ void rescore_gather_kernel(const float* __restrict__ z,
                                      const float* __restrict__ cb,
                                      float* __restrict__ out) {
    const int lane = threadIdx.x & 31, warp = threadIdx.x >> 5;
    const int row = blockIdx.x * 8 + warp;
    __shared__ float wsum[8];
    __shared__ float sred[256];
    __shared__ int s_last;

    const int4 cc = *(const int4*)(g_cand + (size_t)row * 4);
    const int cand[4] = {cc.x, cc.y, cc.z, cc.w};
    const float4* z4 = (const float4*)(z + (size_t)row * DIM);
    float4 a[2], b[4][2];
    float d[4] = {0.f, 0.f, 0.f, 0.f};
#pragma unroll
    for (int l = 0; l < 2; l++) {
        int f = lane + 32 * l;
        a[l] = z4[f];
#pragma unroll
        for (int q = 0; q < 4; q++) {
            b[q][l] = ((const float4*)(cb + (size_t)cand[q] * DIM))[f];
            d[q] += a[l].x * b[q][l].x + a[l].y * b[q][l].y
                  + a[l].z * b[q][l].z + a[l].w * b[q][l].w;
        }
    }
#pragma unroll
    for (int o = 16; o > 0; o >>= 1)
#pragma unroll
        for (int q = 0; q < 4; q++) d[q] += __shfl_xor_sync(0xffffffffu, d[q], o);

    float bv = CUDART_INF_F; int bq = 0, bi = 0x7fffffff;
#pragma unroll
    for (int q = 0; q < 4; q++) {
        float dist = fmaf(-2.f, d[q], __ldg(&g_codenorm[cand[q]]));
        if (dist < bv || (dist == bv && cand[q] < bi)) { bv = dist; bi = cand[q]; bq = q; }
    }

    /* out_ze already written by GEMM prologue; only z_q + loss here */
    float* out_zq = out + (size_t)NROWS * DIM + 1 + (size_t)row * DIM;
    float s = 0.f;
#pragma unroll
    for (int l = 0; l < 2; l++) {
        int f = lane + 32 * l;
        float4 ze = a[l];
        float4 zq = b[bq][l];
        out_zq[f * 4 + 0] = zq.x; out_zq[f * 4 + 1] = zq.y;
        out_zq[f * 4 + 2] = zq.z; out_zq[f * 4 + 3] = zq.w;
        float dx = zq.x - ze.x, dy = zq.y - ze.y, dz = zq.z - ze.z, dw = zq.w - ze.w;
        s += dx * dx + dy * dy + dz * dz + dw * dw;
    }
#pragma unroll
    for (int o = 16; o > 0; o >>= 1) s += __shfl_down_sync(0xffffffffu, s, o);
    if (lane == 0) wsum[warp] = s;
    __syncthreads();
    if (threadIdx.x == 0) {
        float t = 0.f;
#pragma unroll
        for (int wv = 0; wv < 8; wv++) t += wsum[wv];
        g_losspart[blockIdx.x] = t;
        __threadfence();
        unsigned r = atomicAdd(&g_ctr, 1u);
        s_last = (r == NPART - 1) ? 1 : 0;
    }
    __syncthreads();
    if (s_last) {  /* last block: deterministic fixed-order final reduce */
        float t = 0.f;
        for (int i = threadIdx.x; i < NPART; i += 256) t += g_losspart[i];
        sred[threadIdx.x] = t;
        __syncthreads();
        for (int o = 128; o > 0; o >>= 1) {
            if (threadIdx.x < o) sred[threadIdx.x] += sred[threadIdx.x + o];
            __syncthreads();
        }
        if (threadIdx.x == 0)
            out[(size_t)NROWS * DIM] = 2.f * sred[0] / (float)((size_t)NROWS * DIM);
    }
}

extern "C" void kernel_launch(void* const* d_in, const int* in_sizes, int n_in,
                              void* d_out, int out_size) {
    const float* z  = (const float*)d_in[0];
    const float* cb = (const float*)d_in[1];
    float* out = (float*)d_out;

    cudaFuncSetAttribute(vq_mma_kernel, cudaFuncAttributeMaxDynamicSharedMemorySize, GEMM_SMEM);

    preprocess_kernel<<<PC_BLKS + PN_BLKS, 256>>>(cb);
    vq_mma_kernel<<<MTILES, 256, GEMM_SMEM>>>(z, out);
    rescore_gather_kernel<<<NPART, 256>>>(z, cb, out);
}